// round 2
// baseline (speedup 1.0000x reference)
#include <cuda_runtime.h>
#include <cstdint>
#include <cstdio>

// ---------------- problem constants ----------------
constexpr int kD     = 128;
constexpr int kNH    = 8;
constexpr int kHD    = 16;
constexpr int kNW1   = 4096;
constexpr int kL1    = 36;
constexpr int kNW2   = 1024;
constexpr int kL2    = 100;
constexpr int kN1    = (kNW1 / 2) * (kL1 + kL1 / 2);   // 110592
constexpr int kN2    = (kNW2 / 2) * (kL2 + kL2 / 2);   // 76800
constexpr int kNTOK  = kN1 + kN2;                      // 187392  (== 1464 * 128)

static_assert(kNTOK % 128 == 0, "M tile");

// ---------------- device scratch (allocation-free contract) ----------------
__device__ float g_QKin[(size_t)kNTOK * 128];   // gathered f+pos, compact slot order
__device__ float g_QKp [(size_t)kNTOK * 256];   // projected Q(0..127) K(128..255)
__device__ float g_Vp  [(size_t)kNTOK * 128];   // projected V, token order
__device__ float g_O   [(size_t)kNTOK * 128];   // attention output, slot order
__device__ int   g_s2t [kNTOK];                 // slot -> token
__device__ float g_Wt  [128 * 384];             // in_proj_w transposed: Wt[k][n]
__device__ float g_Wot [128 * 128];             // out_proj_w transposed

// ---------------- weight transpose ----------------
__global__ void transpose_w_kernel(const float* __restrict__ Wi,
                                   const float* __restrict__ Wo) {
    int t = blockIdx.x * 256 + threadIdx.x;
    if (t < 384 * 128) {
        int n = t >> 7, k = t & 127;
        g_Wt[k * 384 + n] = Wi[t];
    }
    if (t < 128 * 128) {
        int n = t >> 7, k = t & 127;
        g_Wot[k * 128 + n] = Wo[t];
    }
}

// ---------------- gather: QKin[slot] = feat[inds] + pos ----------------
__global__ __launch_bounds__(256)
void gather_kernel(const float* __restrict__ feat,
                   const float* __restrict__ pos1,
                   const float* __restrict__ pos2,
                   const int* __restrict__ inds1,
                   const int* __restrict__ inds2) {
    int w = blockIdx.x;
    int Lv, slot0;
    const int* inds;
    const float* pos;
    if (w < kNW1) {
        Lv    = (w & 1) ? (kL1 / 2) : kL1;
        slot0 = (w >> 1) * (kL1 + kL1 / 2) + (w & 1) * kL1;
        inds  = inds1 + w * kL1;
        pos   = pos1 + (size_t)w * kL1 * 128;
    } else {
        int w2 = w - kNW1;
        Lv    = (w2 & 1) ? (kL2 / 2) : kL2;
        slot0 = kN1 + (w2 >> 1) * (kL2 + kL2 / 2) + (w2 & 1) * kL2;
        inds  = inds2 + w2 * kL2;
        pos   = pos2 + (size_t)w2 * kL2 * 128;
    }
    for (int t = threadIdx.x; t < Lv * 32; t += 256) {
        int l = t >> 5, c = t & 31;
        int tok = inds[l];
        float4 f = reinterpret_cast<const float4*>(feat + (size_t)tok * 128)[c];
        float4 p = reinterpret_cast<const float4*>(pos + (size_t)l * 128)[c];
        float4 r;
        r.x = f.x + p.x; r.y = f.y + p.y; r.z = f.z + p.z; r.w = f.w + p.w;
        reinterpret_cast<float4*>(g_QKin + (size_t)(slot0 + l) * 128)[c] = r;
        if (c == 0) g_s2t[slot0 + l] = tok;
    }
}

// ---------------- fp32 GEMM, K=128 fixed: C[m][n] = sum_k A[m][k]*W[n][k] + bias ----
// W supplied pre-transposed (Wt[k][n], row stride ldw, column offset c0).
// Optional row scatter via s2t on output.
constexpr int kGemmSmem = (128 * 129 + 128 * 132) * (int)sizeof(float);

__global__ __launch_bounds__(256)
void gemm_k128(const float* __restrict__ A,
               const float* __restrict__ Wt, int ldw, int c0,
               const float* __restrict__ bias,
               float* __restrict__ C, int ldc,
               const int* __restrict__ s2t) {
    extern __shared__ float sm[];
    float* As = sm;              // [128][129]  row-major A tile
    float* Bs = sm + 128 * 129;  // [128][132]  Bs[k][n]
    const int m0 = blockIdx.x * 128;
    const int n0 = blockIdx.y * 128;
    const int tid = threadIdx.x;

    for (int t = tid; t < 4096; t += 256) {
        int r = t >> 5, q = t & 31;
        float4 v = reinterpret_cast<const float4*>(A + (size_t)(m0 + r) * 128)[q];
        float* dst = As + r * 129 + q * 4;
        dst[0] = v.x; dst[1] = v.y; dst[2] = v.z; dst[3] = v.w;
    }
    for (int t = tid; t < 4096; t += 256) {
        int k = t >> 5, q = t & 31;
        float4 v = reinterpret_cast<const float4*>(Wt + (size_t)k * ldw + c0 + n0)[q];
        reinterpret_cast<float4*>(Bs + k * 132)[q] = v;
    }
    __syncthreads();

    const int tx = tid & 15, ty = tid >> 4;
    const float* Ab = As + ty * 8 * 129;
    const float* Bb = Bs + tx * 8;

    float acc[8][8];
#pragma unroll
    for (int i = 0; i < 8; i++)
#pragma unroll
        for (int j = 0; j < 8; j++) acc[i][j] = 0.f;

#pragma unroll 4
    for (int k = 0; k < 128; k++) {
        float a[8];
#pragma unroll
        for (int u = 0; u < 8; u++) a[u] = Ab[u * 129 + k];
        float4 b0 = *reinterpret_cast<const float4*>(Bb + k * 132);
        float4 b1 = *reinterpret_cast<const float4*>(Bb + k * 132 + 4);
        float b[8] = {b0.x, b0.y, b0.z, b0.w, b1.x, b1.y, b1.z, b1.w};
#pragma unroll
        for (int i = 0; i < 8; i++)
#pragma unroll
            for (int j = 0; j < 8; j++)
                acc[i][j] = fmaf(a[i], b[j], acc[i][j]);
    }

    float bb[8];
#pragma unroll
    for (int j = 0; j < 8; j++) bb[j] = bias[n0 + tx * 8 + j];
#pragma unroll
    for (int i = 0; i < 8; i++) {
        int m = m0 + ty * 8 + i;
        int row = s2t ? s2t[m] : m;
        float* Cr = C + (size_t)row * ldc + n0 + tx * 8;
#pragma unroll
        for (int j = 0; j < 8; j++) Cr[j] = acc[i][j] + bb[j];
    }
}

// ---------------- per-window attention ----------------
// smem holds Q,K,V transposed ([128][LP], LP odd => conflict-free column access)
// one warp handles one (head, query) task: lanes over keys for scores,
// (half,c) split for the PV product.
template <int LW>
__global__ __launch_bounds__(256)
void attn_kernel(const float* __restrict__ QKp,
                 const float* __restrict__ Vp,
                 float* __restrict__ O,
                 const int* __restrict__ s2t,
                 int slotbase) {
    constexpr int LP  = LW | 1;            // odd row stride
    constexpr int KPL = (LW + 31) / 32;
    extern __shared__ float sm[];
    float* sQ = sm;
    float* sK = sm + 128 * LP;
    float* sV = sm + 2 * 128 * LP;
    float* sP = sm + 3 * 128 * LP;         // [8][LW]

    const int w = blockIdx.x;
    const int Lv = (w & 1) ? (LW / 2) : LW;
    const int slot0 = slotbase + (w >> 1) * (LW + LW / 2) + (w & 1) * LW;
    const int tid = threadIdx.x;

    for (int t = tid; t < Lv * 32; t += 256) {
        int j = t >> 5, c = t & 31;
        int slot = slot0 + j;
        float4 q = reinterpret_cast<const float4*>(QKp + (size_t)slot * 256)[c];
        float4 k = reinterpret_cast<const float4*>(QKp + (size_t)slot * 256 + 128)[c];
        int tok = s2t[slot];
        float4 v = reinterpret_cast<const float4*>(Vp + (size_t)tok * 128)[c];
        int cc = c * 4;
        sQ[(cc + 0) * LP + j] = q.x; sQ[(cc + 1) * LP + j] = q.y;
        sQ[(cc + 2) * LP + j] = q.z; sQ[(cc + 3) * LP + j] = q.w;
        sK[(cc + 0) * LP + j] = k.x; sK[(cc + 1) * LP + j] = k.y;
        sK[(cc + 2) * LP + j] = k.z; sK[(cc + 3) * LP + j] = k.w;
        sV[(cc + 0) * LP + j] = v.x; sV[(cc + 1) * LP + j] = v.y;
        sV[(cc + 2) * LP + j] = v.z; sV[(cc + 3) * LP + j] = v.w;
    }
    __syncthreads();

    const int warp = tid >> 5, lane = tid & 31;
    float* sPw = sP + warp * LW;
    const int ntask = kNH * Lv;

    for (int task = warp; task < ntask; task += 8) {
        int h = task & 7, i = task >> 3;
        int hb = h * kHD;

        float qv[kHD];
#pragma unroll
        for (int c = 0; c < kHD; c++) qv[c] = sQ[(hb + c) * LP + i];

        float sarr[KPL];
        float mx = -1e30f;
#pragma unroll
        for (int t = 0; t < KPL; t++) {
            int j = lane + 32 * t;
            float s = -1e30f;
            if (j < Lv) {
                s = 0.f;
#pragma unroll
                for (int c = 0; c < kHD; c++)
                    s = fmaf(qv[c], sK[(hb + c) * LP + j], s);
                s *= 0.25f;  // HD^-0.5
            }
            sarr[t] = s;
            mx = fmaxf(mx, s);
        }
#pragma unroll
        for (int o = 16; o > 0; o >>= 1)
            mx = fmaxf(mx, __shfl_xor_sync(0xffffffffu, mx, o));

        float sum = 0.f;
#pragma unroll
        for (int t = 0; t < KPL; t++) {
            int j = lane + 32 * t;
            if (j < Lv) {
                float p = __expf(sarr[t] - mx);
                sum += p;
                sPw[j] = p;
            }
        }
#pragma unroll
        for (int o = 16; o > 0; o >>= 1)
            sum += __shfl_xor_sync(0xffffffffu, sum, o);
        float inv = 1.f / sum;

        __syncwarp();
        int half = lane >> 4, c = lane & 15;
        int jm = (Lv + 1) >> 1;
        int j0 = half ? jm : 0;
        int j1 = half ? Lv : jm;
        float acc = 0.f;
        for (int j = j0; j < j1; j++)
            acc = fmaf(sPw[j], sV[(hb + c) * LP + j], acc);
        acc += __shfl_xor_sync(0xffffffffu, acc, 16);
        if (lane < 16)
            O[(size_t)(slot0 + i) * 128 + hb + c] = acc * inv;
        __syncwarp();  // protect sPw WAR across task iterations
    }
}

// ---------------- launch ----------------
constexpr int kAttnSmem1 = (3 * 128 * (kL1 | 1) + 8 * kL1) * (int)sizeof(float);
constexpr int kAttnSmem2 = (3 * 128 * (kL2 | 1) + 8 * kL2) * (int)sizeof(float);

extern "C" void kernel_launch(void* const* d_in, const int* in_sizes, int n_in,
                              void* d_out, int out_size) {
    const float* feat  = (const float*)d_in[0];
    const float* pos1  = (const float*)d_in[1];
    const float* pos2  = (const float*)d_in[2];
    const float* Wi    = (const float*)d_in[3];
    const float* bi    = (const float*)d_in[4];
    const float* Wo    = (const float*)d_in[5];
    const float* bo    = (const float*)d_in[6];
    const int*   inds1 = (const int*)d_in[7];
    const int*   inds2 = (const int*)d_in[8];
    float* out = (float*)d_out;

    float *QKin, *QKp, *Vp, *Obuf, *Wt, *Wot;
    int* s2t;
    cudaGetSymbolAddress((void**)&QKin, g_QKin);
    cudaGetSymbolAddress((void**)&QKp,  g_QKp);
    cudaGetSymbolAddress((void**)&Vp,   g_Vp);
    cudaGetSymbolAddress((void**)&Obuf, g_O);
    cudaGetSymbolAddress((void**)&s2t,  g_s2t);
    cudaGetSymbolAddress((void**)&Wt,   g_Wt);
    cudaGetSymbolAddress((void**)&Wot,  g_Wot);

    cudaFuncSetAttribute(gemm_k128, cudaFuncAttributeMaxDynamicSharedMemorySize, kGemmSmem);
    cudaFuncSetAttribute(attn_kernel<kL1>, cudaFuncAttributeMaxDynamicSharedMemorySize, kAttnSmem1);
    cudaFuncSetAttribute(attn_kernel<kL2>, cudaFuncAttributeMaxDynamicSharedMemorySize, kAttnSmem2);

    // 1) transpose weights
    transpose_w_kernel<<<192, 256>>>(Wi, Wo);
    // 2) gather f + pos into compact slot space, build slot->token map
    gather_kernel<<<kNW1 + kNW2, 256>>>(feat, pos1, pos2, inds1, inds2);
    // 3) QK projection (slot space): QKp = QKin @ Wqk^T + bqk
    gemm_k128<<<dim3(kNTOK / 128, 2), 256, kGemmSmem>>>(
        QKin, Wt, 384, 0, bi, QKp, 256, nullptr);
    // 4) V projection (token space): Vp = feat @ Wv^T + bv
    gemm_k128<<<dim3(kNTOK / 128, 1), 256, kGemmSmem>>>(
        feat, Wt, 384, 256, bi + 256, Vp, 128, nullptr);
    // 5) windowed attention
    attn_kernel<kL1><<<kNW1, 256, kAttnSmem1>>>(QKp, Vp, Obuf, s2t, 0);
    attn_kernel<kL2><<<kNW2, 256, kAttnSmem2>>>(QKp, Vp, Obuf, s2t, kN1);
    // 6) output projection with row scatter to token order
    gemm_k128<<<dim3(kNTOK / 128, 1), 256, kGemmSmem>>>(
        Obuf, Wot, 128, 0, bo, out, 128, s2t);
}

// round 5
// speedup vs baseline: 2.1157x; 2.1157x over previous
#include <cuda_runtime.h>
#include <cuda_bf16.h>
#include <cstdint>

// ---------------- problem constants ----------------
constexpr int kD     = 128;
constexpr int kNH    = 8;
constexpr int kHD    = 16;
constexpr int kNW1   = 4096;
constexpr int kL1    = 36;
constexpr int kNW2   = 1024;
constexpr int kL2    = 100;
constexpr int kN1    = (kNW1 / 2) * (kL1 + kL1 / 2);   // 110592
constexpr int kN2    = (kNW2 / 2) * (kL2 + kL2 / 2);   // 76800
constexpr int kNTOK  = kN1 + kN2;                      // 187392 == 1464*128

static_assert(kNTOK % 128 == 0, "M tile");

// single shared extern, cast per-kernel
extern __shared__ char smem_raw[];

// ---------------- device scratch ----------------
__device__ float g_QKin[(size_t)kNTOK * 128];
__device__ float g_QKp [(size_t)kNTOK * 256];
__device__ float g_Vp  [(size_t)kNTOK * 128];
__device__ float g_O   [(size_t)kNTOK * 128];
__device__ int   g_s2t [kNTOK];
__device__ __nv_bfloat16 g_Wh[512 * 128];   // rows 0..383 in_proj, 384..511 out_proj (hi)
__device__ __nv_bfloat16 g_Wl[512 * 128];   // (lo residual)

// ---------------- PTX helpers (sm_80+ generic: ldmatrix / mma.sync) --------
__device__ __forceinline__ uint32_t smem_u32(const void* p) {
    uint32_t a;
    asm("{ .reg .u64 t; cvta.to.shared.u64 t, %1; cvt.u32.u64 %0, t; }"
        : "=r"(a) : "l"(p));
    return a;
}
__device__ __forceinline__ void ldsm_x4(uint32_t* r, uint32_t a) {
    asm volatile("ldmatrix.sync.aligned.m8n8.x4.shared.b16 {%0,%1,%2,%3}, [%4];"
                 : "=r"(r[0]), "=r"(r[1]), "=r"(r[2]), "=r"(r[3]) : "r"(a));
}
__device__ __forceinline__ void ldsm_x2(uint32_t* r, uint32_t a) {
    asm volatile("ldmatrix.sync.aligned.m8n8.x2.shared.b16 {%0,%1}, [%2];"
                 : "=r"(r[0]), "=r"(r[1]) : "r"(a));
}
__device__ __forceinline__ void mma_bf16(float* d, const uint32_t* a, const uint32_t* b) {
    asm volatile(
        "mma.sync.aligned.m16n8k16.row.col.f32.bf16.bf16.f32 "
        "{%0,%1,%2,%3}, {%4,%5,%6,%7}, {%8,%9}, {%0,%1,%2,%3};"
        : "+f"(d[0]), "+f"(d[1]), "+f"(d[2]), "+f"(d[3])
        : "r"(a[0]), "r"(a[1]), "r"(a[2]), "r"(a[3]), "r"(b[0]), "r"(b[1]));
}

// ---------------- weight prep: fp32 -> bf16 hi/lo, [512][128] ----------------
__global__ void prep_w_kernel(const float* __restrict__ Wi,
                              const float* __restrict__ Wo) {
    int t = blockIdx.x * 256 + threadIdx.x;
    if (t >= 512 * 128) return;
    float w = (t < 384 * 128) ? Wi[t] : Wo[t - 384 * 128];
    __nv_bfloat16 h = __float2bfloat16(w);
    __nv_bfloat16 l = __float2bfloat16(w - __bfloat162float(h));
    g_Wh[t] = h;
    g_Wl[t] = l;
}

// ---------------- gather: QKin[slot] = feat[inds] + pos ----------------
__global__ __launch_bounds__(256)
void gather_kernel(const float* __restrict__ feat,
                   const float* __restrict__ pos1,
                   const float* __restrict__ pos2,
                   const int* __restrict__ inds1,
                   const int* __restrict__ inds2) {
    int w = blockIdx.x;
    int Lv, slot0;
    const int* inds;
    const float* pos;
    if (w < kNW1) {
        Lv    = (w & 1) ? (kL1 / 2) : kL1;
        slot0 = (w >> 1) * (kL1 + kL1 / 2) + (w & 1) * kL1;
        inds  = inds1 + w * kL1;
        pos   = pos1 + (size_t)w * kL1 * 128;
    } else {
        int w2 = w - kNW1;
        Lv    = (w2 & 1) ? (kL2 / 2) : kL2;
        slot0 = kN1 + (w2 >> 1) * (kL2 + kL2 / 2) + (w2 & 1) * kL2;
        inds  = inds2 + w2 * kL2;
        pos   = pos2 + (size_t)w2 * kL2 * 128;
    }
    for (int t = threadIdx.x; t < Lv * 32; t += 256) {
        int l = t >> 5, c = t & 31;
        int tok = inds[l];
        float4 f = reinterpret_cast<const float4*>(feat + (size_t)tok * 128)[c];
        float4 p = reinterpret_cast<const float4*>(pos + (size_t)l * 128)[c];
        float4 r;
        r.x = f.x + p.x; r.y = f.y + p.y; r.z = f.z + p.z; r.w = f.w + p.w;
        reinterpret_cast<float4*>(g_QKin + (size_t)(slot0 + l) * 128)[c] = r;
        if (c == 0) g_s2t[slot0 + l] = tok;
    }
}

// ---------------- HMMA split-bf16 GEMM ----------------
// C[m][128*nt + n] = sum_k A[m][k] * W[brow0 + 128*nt + n][k] + bias[128*nt + n]
// 128x128x128 tile per block, 8 warps in 2(m) x 4(n); warp tile 64m x 32n.
constexpr int kLds   = 136;                       // padded bf16 row stride
constexpr int kTcSmem = 4 * 128 * kLds * 2;       // 139264 B

__global__ __launch_bounds__(256)
void gemm_tc(const float* __restrict__ A,
             const __nv_bfloat16* __restrict__ Wh,
             const __nv_bfloat16* __restrict__ Wl,
             int brow0, const float* __restrict__ bias,
             float* __restrict__ C, int ldc,
             const int* __restrict__ s2t) {
    __nv_bfloat16* sAh = reinterpret_cast<__nv_bfloat16*>(smem_raw);
    __nv_bfloat16* sAl = sAh + 128 * kLds;
    __nv_bfloat16* sBh = sAh + 2 * 128 * kLds;
    __nv_bfloat16* sBl = sAh + 3 * 128 * kLds;

    const int tid  = threadIdx.x;
    const int wid  = tid >> 5, lane = tid & 31;
    const int m0   = blockIdx.x * 128;
    const int nt   = blockIdx.y;
    const int brow = brow0 + 128 * nt;

    // --- load + split A (fp32 -> bf16 hi/lo) ---
    {
        int r = tid >> 1, ch = (tid & 1) * 64;
        const float4* Ar = reinterpret_cast<const float4*>(A + (size_t)(m0 + r) * 128 + ch);
#pragma unroll
        for (int q = 0; q < 16; q++) {
            float4 v = Ar[q];
            __nv_bfloat162 h01 = __floats2bfloat162_rn(v.x, v.y);
            __nv_bfloat162 h23 = __floats2bfloat162_rn(v.z, v.w);
            __nv_bfloat162 l01 = __floats2bfloat162_rn(
                v.x - __bfloat162float(h01.x), v.y - __bfloat162float(h01.y));
            __nv_bfloat162 l23 = __floats2bfloat162_rn(
                v.z - __bfloat162float(h23.x), v.w - __bfloat162float(h23.y));
            int off = r * kLds + ch + q * 4;
            *reinterpret_cast<__nv_bfloat162*>(sAh + off)     = h01;
            *reinterpret_cast<__nv_bfloat162*>(sAh + off + 2) = h23;
            *reinterpret_cast<__nv_bfloat162*>(sAl + off)     = l01;
            *reinterpret_cast<__nv_bfloat162*>(sAl + off + 2) = l23;
        }
    }
    // --- load B (already split bf16) ---
    {
        int n = tid >> 1, ch = (tid & 1) * 64;
        const uint4* Bh4 = reinterpret_cast<const uint4*>(Wh + (size_t)(brow + n) * 128 + ch);
        const uint4* Bl4 = reinterpret_cast<const uint4*>(Wl + (size_t)(brow + n) * 128 + ch);
#pragma unroll
        for (int q = 0; q < 8; q++) {
            *reinterpret_cast<uint4*>(sBh + n * kLds + ch + q * 8) = Bh4[q];
            *reinterpret_cast<uint4*>(sBl + n * kLds + ch + q * 8) = Bl4[q];
        }
    }
    __syncthreads();

    const int wm = (wid & 1) * 64;       // warp m offset
    const int wn = (wid >> 1) * 32;      // warp n offset
    const uint32_t sAh_u = smem_u32(sAh);
    const uint32_t sBh_u = smem_u32(sBh);
    const uint32_t loOff = (uint32_t)(128 * kLds * 2);  // bytes from hi to lo tile

    const int aro = (lane & 7) + ((lane >> 3) & 1) * 8; // A ldmatrix row-in-16
    const int aco = (lane >> 4) * 8;                    // A ldmatrix col-in-16
    const int bl  = lane & 15;                          // B uses lanes 0..15
    const int bro = bl & 7;
    const int bco = ((bl >> 3) & 1) * 8;

    float acc[4][4][4];
#pragma unroll
    for (int mi = 0; mi < 4; mi++)
#pragma unroll
        for (int ni = 0; ni < 4; ni++)
#pragma unroll
            for (int j = 0; j < 4; j++) acc[mi][ni][j] = 0.f;

#pragma unroll
    for (int ks = 0; ks < 8; ks++) {
        uint32_t ah[4][4], al[4][4], bh[4][2], blo[4][2];
#pragma unroll
        for (int mi = 0; mi < 4; mi++) {
            uint32_t addr = sAh_u +
                (uint32_t)(((wm + mi * 16 + aro) * kLds + ks * 16 + aco) * 2);
            ldsm_x4(ah[mi], addr);
            ldsm_x4(al[mi], addr + loOff);
        }
#pragma unroll
        for (int ni = 0; ni < 4; ni++) {
            uint32_t addr = sBh_u +
                (uint32_t)(((wn + ni * 8 + bro) * kLds + ks * 16 + bco) * 2);
            ldsm_x2(bh[ni], addr);
            ldsm_x2(blo[ni], addr + loOff);
        }
#pragma unroll
        for (int mi = 0; mi < 4; mi++)
#pragma unroll
            for (int ni = 0; ni < 4; ni++) {
                mma_bf16(acc[mi][ni], ah[mi], bh[ni]);
                mma_bf16(acc[mi][ni], ah[mi], blo[ni]);
                mma_bf16(acc[mi][ni], al[mi], bh[ni]);
            }
    }

    // --- epilogue: add bias, scatter rows ---
    const int g = lane >> 2, tig = lane & 3;
#pragma unroll
    for (int mi = 0; mi < 4; mi++) {
        int r0 = m0 + wm + mi * 16 + g;
        int r1 = r0 + 8;
        int or0 = s2t ? s2t[r0] : r0;
        int or1 = s2t ? s2t[r1] : r1;
#pragma unroll
        for (int ni = 0; ni < 4; ni++) {
            int col = wn + ni * 8 + 2 * tig;
            float b0 = bias[128 * nt + col];
            float b1 = bias[128 * nt + col + 1];
            *reinterpret_cast<float2*>(C + (size_t)or0 * ldc + 128 * nt + col) =
                make_float2(acc[mi][ni][0] + b0, acc[mi][ni][1] + b1);
            *reinterpret_cast<float2*>(C + (size_t)or1 * ldc + 128 * nt + col) =
                make_float2(acc[mi][ni][2] + b0, acc[mi][ni][3] + b1);
        }
    }
}

// ---------------- per-window attention (4-query batched) ----------------
template <int LW>
__global__ __launch_bounds__(256)
void attn_kernel(const float* __restrict__ QKp,
                 const float* __restrict__ Vp,
                 float* __restrict__ O,
                 const int* __restrict__ s2t,
                 int slotbase) {
    constexpr int LP  = LW | 1;
    constexpr int KPL = (LW + 31) / 32;
    float* sQ = reinterpret_cast<float*>(smem_raw);
    float* sK = sQ + 128 * LP;
    float* sV = sQ + 2 * 128 * LP;
    float* sP = sQ + 3 * 128 * LP;          // [8 warps][4][LW]

    const int w = blockIdx.x;
    const int Lv = (w & 1) ? (LW / 2) : LW;
    const int slot0 = slotbase + (w >> 1) * (LW + LW / 2) + (w & 1) * LW;
    const int tid = threadIdx.x;

    for (int t = tid; t < Lv * 32; t += 256) {
        int j = t >> 5, c = t & 31;
        int slot = slot0 + j;
        float4 q = reinterpret_cast<const float4*>(QKp + (size_t)slot * 256)[c];
        float4 k = reinterpret_cast<const float4*>(QKp + (size_t)slot * 256 + 128)[c];
        int tok = s2t[slot];
        float4 v = reinterpret_cast<const float4*>(Vp + (size_t)tok * 128)[c];
        int cc = c * 4;
        sQ[(cc + 0) * LP + j] = q.x; sQ[(cc + 1) * LP + j] = q.y;
        sQ[(cc + 2) * LP + j] = q.z; sQ[(cc + 3) * LP + j] = q.w;
        sK[(cc + 0) * LP + j] = k.x; sK[(cc + 1) * LP + j] = k.y;
        sK[(cc + 2) * LP + j] = k.z; sK[(cc + 3) * LP + j] = k.w;
        sV[(cc + 0) * LP + j] = v.x; sV[(cc + 1) * LP + j] = v.y;
        sV[(cc + 2) * LP + j] = v.z; sV[(cc + 3) * LP + j] = v.w;
    }
    __syncthreads();

    const int warp = tid >> 5, lane = tid & 31;
    float* sPw = sP + warp * 4 * LW;
    const int ngrp = kNH * ((Lv + 3) >> 2);

    for (int g = warp; g < ngrp; g += 8) {
        int h = g & 7, i0 = (g >> 3) << 2;
        int hb = h * kHD;

        float qv[4][kHD];
#pragma unroll
        for (int q = 0; q < 4; q++) {
            bool act = (i0 + q) < Lv;
#pragma unroll
            for (int c = 0; c < kHD; c++)
                qv[q][c] = act ? sQ[(hb + c) * LP + (i0 + q)] : 0.f;
        }

        float sarr[4][KPL];
        float mx[4] = {-1e30f, -1e30f, -1e30f, -1e30f};
#pragma unroll
        for (int t = 0; t < KPL; t++) {
            int j = lane + 32 * t;
            if (j < Lv) {
                float kc[kHD];
#pragma unroll
                for (int c = 0; c < kHD; c++) kc[c] = sK[(hb + c) * LP + j];
#pragma unroll
                for (int q = 0; q < 4; q++) {
                    float s = 0.f;
#pragma unroll
                    for (int c = 0; c < kHD; c++) s = fmaf(qv[q][c], kc[c], s);
                    s *= 0.25f;
                    sarr[q][t] = s;
                    mx[q] = fmaxf(mx[q], s);
                }
            } else {
#pragma unroll
                for (int q = 0; q < 4; q++) sarr[q][t] = -1e30f;
            }
        }
#pragma unroll
        for (int o = 16; o > 0; o >>= 1)
#pragma unroll
            for (int q = 0; q < 4; q++)
                mx[q] = fmaxf(mx[q], __shfl_xor_sync(0xffffffffu, mx[q], o));

        float sum[4] = {0.f, 0.f, 0.f, 0.f};
#pragma unroll
        for (int t = 0; t < KPL; t++) {
            int j = lane + 32 * t;
            if (j < Lv) {
#pragma unroll
                for (int q = 0; q < 4; q++) {
                    float p = __expf(sarr[q][t] - mx[q]);
                    sum[q] += p;
                    sPw[q * LW + j] = p;
                }
            }
        }
#pragma unroll
        for (int o = 16; o > 0; o >>= 1)
#pragma unroll
            for (int q = 0; q < 4; q++)
                sum[q] += __shfl_xor_sync(0xffffffffu, sum[q], o);

        __syncwarp();
        int half = lane >> 4, c = lane & 15;
        int jm = (Lv + 1) >> 1;
        int j0 = half ? jm : 0, j1 = half ? Lv : jm;
        float acc[4] = {0.f, 0.f, 0.f, 0.f};
        for (int j = j0; j < j1; j++) {
            float vv = sV[(hb + c) * LP + j];
#pragma unroll
            for (int q = 0; q < 4; q++)
                acc[q] = fmaf(sPw[q * LW + j], vv, acc[q]);
        }
#pragma unroll
        for (int q = 0; q < 4; q++)
            acc[q] += __shfl_xor_sync(0xffffffffu, acc[q], 16);
        if (lane < 16) {
#pragma unroll
            for (int q = 0; q < 4; q++) {
                int i = i0 + q;
                if (i < Lv)
                    O[(size_t)(slot0 + i) * 128 + hb + c] = acc[q] / sum[q];
            }
        }
        __syncwarp();  // WAR on sPw across group iterations
    }
}

// ---------------- launch ----------------
constexpr int kAttnSmem1 = (3 * 128 * (kL1 | 1) + 32 * kL1) * (int)sizeof(float);
constexpr int kAttnSmem2 = (3 * 128 * (kL2 | 1) + 32 * kL2) * (int)sizeof(float);

extern "C" void kernel_launch(void* const* d_in, const int* in_sizes, int n_in,
                              void* d_out, int out_size) {
    const float* feat  = (const float*)d_in[0];
    const float* pos1  = (const float*)d_in[1];
    const float* pos2  = (const float*)d_in[2];
    const float* Wi    = (const float*)d_in[3];
    const float* bi    = (const float*)d_in[4];
    const float* Wo    = (const float*)d_in[5];
    const float* bo    = (const float*)d_in[6];
    const int*   inds1 = (const int*)d_in[7];
    const int*   inds2 = (const int*)d_in[8];
    float* out = (float*)d_out;

    float *QKin, *QKp, *Vp, *Obuf;
    __nv_bfloat16 *Wh, *Wl;
    int* s2t;
    cudaGetSymbolAddress((void**)&QKin, g_QKin);
    cudaGetSymbolAddress((void**)&QKp,  g_QKp);
    cudaGetSymbolAddress((void**)&Vp,   g_Vp);
    cudaGetSymbolAddress((void**)&Obuf, g_O);
    cudaGetSymbolAddress((void**)&s2t,  g_s2t);
    cudaGetSymbolAddress((void**)&Wh,   g_Wh);
    cudaGetSymbolAddress((void**)&Wl,   g_Wl);

    cudaFuncSetAttribute(gemm_tc, cudaFuncAttributeMaxDynamicSharedMemorySize, kTcSmem);
    cudaFuncSetAttribute(attn_kernel<kL1>, cudaFuncAttributeMaxDynamicSharedMemorySize, kAttnSmem1);
    cudaFuncSetAttribute(attn_kernel<kL2>, cudaFuncAttributeMaxDynamicSharedMemorySize, kAttnSmem2);

    // 1) split weights into bf16 hi/lo
    prep_w_kernel<<<256, 256>>>(Wi, Wo);
    // 2) gather f + pos into compact slot space
    gather_kernel<<<kNW1 + kNW2, 256>>>(feat, pos1, pos2, inds1, inds2);
    // 3) QK projection: QKp[:,0:128]=Q, [:,128:256]=K
    gemm_tc<<<dim3(kNTOK / 128, 2), 256, kTcSmem>>>(
        QKin, Wh, Wl, 0, bi, QKp, 256, nullptr);
    // 4) V projection (token space)
    gemm_tc<<<dim3(kNTOK / 128, 1), 256, kTcSmem>>>(
        feat, Wh, Wl, 256, bi + 256, Vp, 128, nullptr);
    // 5) windowed attention
    attn_kernel<kL1><<<kNW1, 256, kAttnSmem1>>>(QKp, Vp, Obuf, s2t, 0);
    attn_kernel<kL2><<<kNW2, 256, kAttnSmem2>>>(QKp, Vp, Obuf, s2t, kN1);
    // 6) output projection with row scatter (bijective -> no init/atomics)
    gemm_tc<<<dim3(kNTOK / 128, 1), 256, kTcSmem>>>(
        Obuf, Wh, Wl, 384, bo, out, 128, s2t);
}

// round 6
// speedup vs baseline: 2.8722x; 1.3575x over previous
#include <cuda_runtime.h>
#include <cuda_bf16.h>
#include <cstdint>

// ---------------- problem constants ----------------
constexpr int kD     = 128;
constexpr int kNH    = 8;
constexpr int kHD    = 16;
constexpr int kNW1   = 4096;
constexpr int kL1    = 36;
constexpr int kNW2   = 1024;
constexpr int kL2    = 100;
constexpr int kN1    = (kNW1 / 2) * (kL1 + kL1 / 2);   // 110592
constexpr int kN2    = (kNW2 / 2) * (kL2 + kL2 / 2);   // 76800
constexpr int kNTOK  = kN1 + kN2;                      // 187392 == 1464*128

static_assert(kNTOK % 128 == 0, "M tile");

extern __shared__ char smem_raw[];

// ---------------- device scratch ----------------
__device__ float g_QKin[(size_t)kNTOK * 128];
__device__ float g_QKp [(size_t)kNTOK * 256];
__device__ float g_Vp  [(size_t)kNTOK * 128];
__device__ float g_O   [(size_t)kNTOK * 128];
__device__ int   g_s2t [kNTOK];
__device__ __nv_bfloat16 g_Wh[512 * 128];   // rows 0..383 in_proj, 384..511 out_proj
__device__ __nv_bfloat16 g_Wl[512 * 128];

// ---------------- PTX helpers (sm_80+ generic) ----------------
__device__ __forceinline__ uint32_t smem_u32(const void* p) {
    uint32_t a;
    asm("{ .reg .u64 t; cvta.to.shared.u64 t, %1; cvt.u32.u64 %0, t; }"
        : "=r"(a) : "l"(p));
    return a;
}
__device__ __forceinline__ void ldsm_x4(uint32_t* r, uint32_t a) {
    asm volatile("ldmatrix.sync.aligned.m8n8.x4.shared.b16 {%0,%1,%2,%3}, [%4];"
                 : "=r"(r[0]), "=r"(r[1]), "=r"(r[2]), "=r"(r[3]) : "r"(a));
}
__device__ __forceinline__ void ldsm_x2(uint32_t* r, uint32_t a) {
    asm volatile("ldmatrix.sync.aligned.m8n8.x2.shared.b16 {%0,%1}, [%2];"
                 : "=r"(r[0]), "=r"(r[1]) : "r"(a));
}
__device__ __forceinline__ void ldsm_x2_trans(uint32_t* r, uint32_t a) {
    asm volatile("ldmatrix.sync.aligned.m8n8.x2.trans.shared.b16 {%0,%1}, [%2];"
                 : "=r"(r[0]), "=r"(r[1]) : "r"(a));
}
__device__ __forceinline__ void mma_bf16(float* d, const uint32_t* a, const uint32_t* b) {
    asm volatile(
        "mma.sync.aligned.m16n8k16.row.col.f32.bf16.bf16.f32 "
        "{%0,%1,%2,%3}, {%4,%5,%6,%7}, {%8,%9}, {%0,%1,%2,%3};"
        : "+f"(d[0]), "+f"(d[1]), "+f"(d[2]), "+f"(d[3])
        : "r"(a[0]), "r"(a[1]), "r"(a[2]), "r"(a[3]), "r"(b[0]), "r"(b[1]));
}
__device__ __forceinline__ void pack_split(float x, float y, uint32_t& h, uint32_t& l) {
    __nv_bfloat162 hh = __floats2bfloat162_rn(x, y);
    __nv_bfloat162 ll = __floats2bfloat162_rn(x - __bfloat162float(hh.x),
                                              y - __bfloat162float(hh.y));
    h = *reinterpret_cast<uint32_t*>(&hh);
    l = *reinterpret_cast<uint32_t*>(&ll);
}
__device__ __forceinline__ void split_store(__nv_bfloat16* hi, __nv_bfloat16* lo,
                                            int idx, float4 v) {
    __nv_bfloat162 h01 = __floats2bfloat162_rn(v.x, v.y);
    __nv_bfloat162 h23 = __floats2bfloat162_rn(v.z, v.w);
    __nv_bfloat162 l01 = __floats2bfloat162_rn(v.x - __bfloat162float(h01.x),
                                               v.y - __bfloat162float(h01.y));
    __nv_bfloat162 l23 = __floats2bfloat162_rn(v.z - __bfloat162float(h23.x),
                                               v.w - __bfloat162float(h23.y));
    *reinterpret_cast<__nv_bfloat162*>(hi + idx)     = h01;
    *reinterpret_cast<__nv_bfloat162*>(hi + idx + 2) = h23;
    *reinterpret_cast<__nv_bfloat162*>(lo + idx)     = l01;
    *reinterpret_cast<__nv_bfloat162*>(lo + idx + 2) = l23;
}

// ---------------- weight prep ----------------
__global__ void prep_w_kernel(const float* __restrict__ Wi,
                              const float* __restrict__ Wo) {
    int t = blockIdx.x * 256 + threadIdx.x;
    if (t >= 512 * 128) return;
    float w = (t < 384 * 128) ? Wi[t] : Wo[t - 384 * 128];
    __nv_bfloat16 h = __float2bfloat16(w);
    __nv_bfloat16 l = __float2bfloat16(w - __bfloat162float(h));
    g_Wh[t] = h;
    g_Wl[t] = l;
}

// ---------------- gather ----------------
__global__ __launch_bounds__(256)
void gather_kernel(const float* __restrict__ feat,
                   const float* __restrict__ pos1,
                   const float* __restrict__ pos2,
                   const int* __restrict__ inds1,
                   const int* __restrict__ inds2) {
    int w = blockIdx.x;
    int Lv, slot0;
    const int* inds;
    const float* pos;
    if (w < kNW1) {
        Lv    = (w & 1) ? (kL1 / 2) : kL1;
        slot0 = (w >> 1) * (kL1 + kL1 / 2) + (w & 1) * kL1;
        inds  = inds1 + w * kL1;
        pos   = pos1 + (size_t)w * kL1 * 128;
    } else {
        int w2 = w - kNW1;
        Lv    = (w2 & 1) ? (kL2 / 2) : kL2;
        slot0 = kN1 + (w2 >> 1) * (kL2 + kL2 / 2) + (w2 & 1) * kL2;
        inds  = inds2 + w2 * kL2;
        pos   = pos2 + (size_t)w2 * kL2 * 128;
    }
    for (int t = threadIdx.x; t < Lv * 32; t += 256) {
        int l = t >> 5, c = t & 31;
        int tok = inds[l];
        float4 f = reinterpret_cast<const float4*>(feat + (size_t)tok * 128)[c];
        float4 p = reinterpret_cast<const float4*>(pos + (size_t)l * 128)[c];
        float4 r;
        r.x = f.x + p.x; r.y = f.y + p.y; r.z = f.z + p.z; r.w = f.w + p.w;
        reinterpret_cast<float4*>(g_QKin + (size_t)(slot0 + l) * 128)[c] = r;
        if (c == 0) g_s2t[slot0 + l] = tok;
    }
}

// ---------------- HMMA split-bf16 GEMM (M-tile 64 for 2 blocks/SM) --------
constexpr int kLds  = 136;
constexpr int kMT   = 64;
constexpr int kTcSmem = (2 * kMT + 2 * 128) * kLds * 2;   // 104448 B

__global__ __launch_bounds__(256)
void gemm_tc(const float* __restrict__ A,
             const __nv_bfloat16* __restrict__ Wh,
             const __nv_bfloat16* __restrict__ Wl,
             int brow0, const float* __restrict__ bias,
             float* __restrict__ C, int ldc,
             const int* __restrict__ s2t) {
    __nv_bfloat16* sAh = reinterpret_cast<__nv_bfloat16*>(smem_raw);
    __nv_bfloat16* sAl = sAh + kMT * kLds;
    __nv_bfloat16* sBh = sAh + 2 * kMT * kLds;
    __nv_bfloat16* sBl = sBh + 128 * kLds;

    const int tid  = threadIdx.x;
    const int wid  = tid >> 5, lane = tid & 31;
    const int m0   = blockIdx.x * kMT;
    const int nt   = blockIdx.y;
    const int brow = brow0 + 128 * nt;

    // --- load + split A (fp32 -> bf16 hi/lo): 64 rows ---
    {
        int r = tid >> 2, ch = (tid & 3) * 32;
        const float4* Ar = reinterpret_cast<const float4*>(A + (size_t)(m0 + r) * 128 + ch);
#pragma unroll
        for (int q = 0; q < 8; q++) {
            float4 v = Ar[q];
            split_store(sAh, sAl, r * kLds + ch + q * 4, v);
        }
    }
    // --- load B (already split bf16): 128 rows ---
    {
        int n = tid >> 1, ch = (tid & 1) * 64;
        const uint4* Bh4 = reinterpret_cast<const uint4*>(Wh + (size_t)(brow + n) * 128 + ch);
        const uint4* Bl4 = reinterpret_cast<const uint4*>(Wl + (size_t)(brow + n) * 128 + ch);
#pragma unroll
        for (int q = 0; q < 8; q++) {
            *reinterpret_cast<uint4*>(sBh + n * kLds + ch + q * 8) = Bh4[q];
            *reinterpret_cast<uint4*>(sBl + n * kLds + ch + q * 8) = Bl4[q];
        }
    }
    __syncthreads();

    const int wm = (wid & 1) * 32;       // warp m offset (2 x 32)
    const int wn = (wid >> 1) * 32;      // warp n offset (4 x 32)
    const uint32_t sAh_u = smem_u32(sAh);
    const uint32_t sBh_u = smem_u32(sBh);
    const uint32_t aLo = (uint32_t)(kMT * kLds * 2);
    const uint32_t bLo = (uint32_t)(128 * kLds * 2);

    const int aro = lane & 15;
    const int aco = (lane >> 4) * 8;
    const int bl  = lane & 15;
    const int bro = bl & 7;
    const int bco = ((bl >> 3) & 1) * 8;

    float acc[2][4][4];
#pragma unroll
    for (int mi = 0; mi < 2; mi++)
#pragma unroll
        for (int ni = 0; ni < 4; ni++)
#pragma unroll
            for (int j = 0; j < 4; j++) acc[mi][ni][j] = 0.f;

#pragma unroll
    for (int ks = 0; ks < 8; ks++) {
        uint32_t ah[2][4], al[2][4], bh[4][2], blo[4][2];
#pragma unroll
        for (int mi = 0; mi < 2; mi++) {
            uint32_t addr = sAh_u +
                (uint32_t)(((wm + mi * 16 + aro) * kLds + ks * 16 + aco) * 2);
            ldsm_x4(ah[mi], addr);
            ldsm_x4(al[mi], addr + aLo);
        }
#pragma unroll
        for (int ni = 0; ni < 4; ni++) {
            uint32_t addr = sBh_u +
                (uint32_t)(((wn + ni * 8 + bro) * kLds + ks * 16 + bco) * 2);
            ldsm_x2(bh[ni], addr);
            ldsm_x2(blo[ni], addr + bLo);
        }
#pragma unroll
        for (int mi = 0; mi < 2; mi++)
#pragma unroll
            for (int ni = 0; ni < 4; ni++) {
                mma_bf16(acc[mi][ni], ah[mi], bh[ni]);
                mma_bf16(acc[mi][ni], ah[mi], blo[ni]);
                mma_bf16(acc[mi][ni], al[mi], bh[ni]);
            }
    }

    // --- epilogue: add bias, scatter rows ---
    const int g = lane >> 2, tig = lane & 3;
#pragma unroll
    for (int mi = 0; mi < 2; mi++) {
        int r0 = m0 + wm + mi * 16 + g;
        int r1 = r0 + 8;
        int or0 = s2t ? s2t[r0] : r0;
        int or1 = s2t ? s2t[r1] : r1;
#pragma unroll
        for (int ni = 0; ni < 4; ni++) {
            int col = wn + ni * 8 + 2 * tig;
            float b0 = bias[128 * nt + col];
            float b1 = bias[128 * nt + col + 1];
            *reinterpret_cast<float2*>(C + (size_t)or0 * ldc + 128 * nt + col) =
                make_float2(acc[mi][ni][0] + b0, acc[mi][ni][1] + b1);
            *reinterpret_cast<float2*>(C + (size_t)or1 * ldc + 128 * nt + col) =
                make_float2(acc[mi][ni][2] + b0, acc[mi][ni][3] + b1);
        }
    }
}

// ---------------- MMA attention: one warp per head ----------------
// S_h = (Q_h * 0.25) K_h^T  (m16n8k16, split-bf16 3-product),
// softmax on C fragments (quad shuffles), P repacked as A fragments,
// O_h = P V_h (V via ldmatrix.trans, split-bf16 3-product).
template <int LW>
__global__ __launch_bounds__(256)
void attn_mma(const float* __restrict__ QKp,
              const float* __restrict__ Vp,
              float* __restrict__ O,
              const int* __restrict__ s2t,
              int slotbase) {
    constexpr int RowsP  = ((LW + 15) / 16) * 16;       // 48 / 112
    constexpr int NTmax  = (LW + 7) / 8;                // 5 / 13
    constexpr int NTPmax = (NTmax + 1) & ~1;            // 6 / 14
    constexpr int Lstr   = 136;
    constexpr int TSZ    = RowsP * Lstr;
    static_assert(NTPmax * 8 <= RowsP, "key pad fits");

    __nv_bfloat16* sQh = reinterpret_cast<__nv_bfloat16*>(smem_raw);
    __nv_bfloat16* sQl = sQh + TSZ;
    __nv_bfloat16* sKh = sQh + 2 * TSZ;
    __nv_bfloat16* sKl = sQh + 3 * TSZ;
    __nv_bfloat16* sVh = sQh + 4 * TSZ;
    __nv_bfloat16* sVl = sQh + 5 * TSZ;

    const int w = blockIdx.x;
    const int Lv = (w & 1) ? (LW / 2) : LW;
    const int slot0 = slotbase + (w >> 1) * (LW + LW / 2) + (w & 1) * LW;
    const int tid = threadIdx.x;

    // --- fill smem: Q(scaled)/K/V hi+lo, zero pad rows ---
    for (int t = tid; t < RowsP * 32; t += 256) {
        int j = t >> 5, c = t & 31;
        int idx = j * Lstr + c * 4;
        if (j < Lv) {
            int slot = slot0 + j;
            float4 q = reinterpret_cast<const float4*>(QKp + (size_t)slot * 256)[c];
            float4 k = reinterpret_cast<const float4*>(QKp + (size_t)slot * 256 + 128)[c];
            float4 v = reinterpret_cast<const float4*>(Vp + (size_t)g_s2t[slot] * 128)[c];
            q.x *= 0.25f; q.y *= 0.25f; q.z *= 0.25f; q.w *= 0.25f;
            split_store(sQh, sQl, idx, q);
            split_store(sKh, sKl, idx, k);
            split_store(sVh, sVl, idx, v);
        } else {
            uint2 z = make_uint2(0u, 0u);
            *reinterpret_cast<uint2*>(sQh + idx) = z;
            *reinterpret_cast<uint2*>(sQl + idx) = z;
            *reinterpret_cast<uint2*>(sKh + idx) = z;
            *reinterpret_cast<uint2*>(sKl + idx) = z;
            *reinterpret_cast<uint2*>(sVh + idx) = z;
            *reinterpret_cast<uint2*>(sVl + idx) = z;
        }
    }
    __syncthreads();

    const int warp = tid >> 5, lane = tid & 31;
    const int hb = warp * 16;                 // head column base
    const int T = lane >> 2, i4 = lane & 3;
    const int bl = lane & 15;
    const int NT  = (Lv + 7) / 8;
    const int NTP = (NT + 1) & ~1;
    const int MT  = (Lv + 15) / 16;

    const uint32_t uQh = smem_u32(sQh);
    const uint32_t uKh = smem_u32(sKh);
    const uint32_t uVh = smem_u32(sVh);
    const uint32_t LO  = (uint32_t)(TSZ * 2);   // hi -> lo byte offset

    for (int mi = 0; mi < MT; mi++) {
        uint32_t qh[4], ql[4];
        {
            int row = mi * 16 + (lane & 15);
            uint32_t a = uQh + (uint32_t)((row * Lstr + hb + (lane >> 4) * 8) * 2);
            ldsm_x4(qh, a);
            ldsm_x4(ql, a + LO);
        }

        float s[NTPmax][4];
        float m0 = -1e30f, m1 = -1e30f;
#pragma unroll
        for (int nj = 0; nj < NTPmax; nj++) {
            if (nj < NT) {
                uint32_t kh[2], kl[2];
                int row = nj * 8 + (bl & 7);
                uint32_t a = uKh + (uint32_t)((row * Lstr + hb + ((bl >> 3) & 1) * 8) * 2);
                ldsm_x2(kh, a);
                ldsm_x2(kl, a + LO);
                s[nj][0] = s[nj][1] = s[nj][2] = s[nj][3] = 0.f;
                mma_bf16(s[nj], qh, kh);
                mma_bf16(s[nj], qh, kl);
                mma_bf16(s[nj], ql, kh);
                int j0 = nj * 8 + 2 * i4;
                if (j0 >= Lv)     { s[nj][0] = -1e30f; s[nj][2] = -1e30f; }
                if (j0 + 1 >= Lv) { s[nj][1] = -1e30f; s[nj][3] = -1e30f; }
                m0 = fmaxf(m0, fmaxf(s[nj][0], s[nj][1]));
                m1 = fmaxf(m1, fmaxf(s[nj][2], s[nj][3]));
            }
        }
        m0 = fmaxf(m0, __shfl_xor_sync(0xffffffffu, m0, 1));
        m0 = fmaxf(m0, __shfl_xor_sync(0xffffffffu, m0, 2));
        m1 = fmaxf(m1, __shfl_xor_sync(0xffffffffu, m1, 1));
        m1 = fmaxf(m1, __shfl_xor_sync(0xffffffffu, m1, 2));

        float sum0 = 0.f, sum1 = 0.f;
#pragma unroll
        for (int nj = 0; nj < NTPmax; nj++) {
            if (nj < NT) {
                s[nj][0] = __expf(s[nj][0] - m0);
                s[nj][1] = __expf(s[nj][1] - m0);
                s[nj][2] = __expf(s[nj][2] - m1);
                s[nj][3] = __expf(s[nj][3] - m1);
                sum0 += s[nj][0] + s[nj][1];
                sum1 += s[nj][2] + s[nj][3];
            } else {
                s[nj][0] = s[nj][1] = s[nj][2] = s[nj][3] = 0.f;
            }
        }
        sum0 += __shfl_xor_sync(0xffffffffu, sum0, 1);
        sum0 += __shfl_xor_sync(0xffffffffu, sum0, 2);
        sum1 += __shfl_xor_sync(0xffffffffu, sum1, 1);
        sum1 += __shfl_xor_sync(0xffffffffu, sum1, 2);

        // PV: P fragments repacked from S fragments, V via ldmatrix.trans
        float o0[4] = {0.f, 0.f, 0.f, 0.f};
        float o1[4] = {0.f, 0.f, 0.f, 0.f};
#pragma unroll
        for (int kj = 0; kj < NTPmax / 2; kj++) {
            if (kj * 2 < NTP) {
                uint32_t ah[4], al[4];
                pack_split(s[2 * kj][0],     s[2 * kj][1],     ah[0], al[0]);
                pack_split(s[2 * kj][2],     s[2 * kj][3],     ah[1], al[1]);
                pack_split(s[2 * kj + 1][0], s[2 * kj + 1][1], ah[2], al[2]);
                pack_split(s[2 * kj + 1][2], s[2 * kj + 1][3], ah[3], al[3]);
                int row = kj * 16 + bl;
                uint32_t a0 = uVh + (uint32_t)((row * Lstr + hb) * 2);
                uint32_t vh[2], vl[2];
                ldsm_x2_trans(vh, a0);
                ldsm_x2_trans(vl, a0 + LO);
                mma_bf16(o0, ah, vh);
                mma_bf16(o0, ah, vl);
                mma_bf16(o0, al, vh);
                ldsm_x2_trans(vh, a0 + 16);
                ldsm_x2_trans(vl, a0 + 16 + LO);
                mma_bf16(o1, ah, vh);
                mma_bf16(o1, ah, vl);
                mma_bf16(o1, al, vh);
            }
        }

        float inv0 = 1.f / sum0, inv1 = 1.f / sum1;
        int r0 = mi * 16 + T, r1 = r0 + 8;
        int col = hb + 2 * i4;
        if (r0 < Lv) {
            float* p = O + (size_t)(slot0 + r0) * 128 + col;
            *reinterpret_cast<float2*>(p)     = make_float2(o0[0] * inv0, o0[1] * inv0);
            *reinterpret_cast<float2*>(p + 8) = make_float2(o1[0] * inv0, o1[1] * inv0);
        }
        if (r1 < Lv) {
            float* p = O + (size_t)(slot0 + r1) * 128 + col;
            *reinterpret_cast<float2*>(p)     = make_float2(o0[2] * inv1, o0[3] * inv1);
            *reinterpret_cast<float2*>(p + 8) = make_float2(o1[2] * inv1, o1[3] * inv1);
        }
    }
}

// ---------------- launch ----------------
constexpr int kAtSmem1 = 6 * (((kL1 + 15) / 16) * 16) * 136 * 2;   // 78336
constexpr int kAtSmem2 = 6 * (((kL2 + 15) / 16) * 16) * 136 * 2;   // 182784

extern "C" void kernel_launch(void* const* d_in, const int* in_sizes, int n_in,
                              void* d_out, int out_size) {
    const float* feat  = (const float*)d_in[0];
    const float* pos1  = (const float*)d_in[1];
    const float* pos2  = (const float*)d_in[2];
    const float* Wi    = (const float*)d_in[3];
    const float* bi    = (const float*)d_in[4];
    const float* Wo    = (const float*)d_in[5];
    const float* bo    = (const float*)d_in[6];
    const int*   inds1 = (const int*)d_in[7];
    const int*   inds2 = (const int*)d_in[8];
    float* out = (float*)d_out;

    float *QKin, *QKp, *Vp, *Obuf;
    __nv_bfloat16 *Wh, *Wl;
    int* s2t;
    cudaGetSymbolAddress((void**)&QKin, g_QKin);
    cudaGetSymbolAddress((void**)&QKp,  g_QKp);
    cudaGetSymbolAddress((void**)&Vp,   g_Vp);
    cudaGetSymbolAddress((void**)&Obuf, g_O);
    cudaGetSymbolAddress((void**)&s2t,  g_s2t);
    cudaGetSymbolAddress((void**)&Wh,   g_Wh);
    cudaGetSymbolAddress((void**)&Wl,   g_Wl);

    cudaFuncSetAttribute(gemm_tc, cudaFuncAttributeMaxDynamicSharedMemorySize, kTcSmem);
    cudaFuncSetAttribute(attn_mma<kL1>, cudaFuncAttributeMaxDynamicSharedMemorySize, kAtSmem1);
    cudaFuncSetAttribute(attn_mma<kL2>, cudaFuncAttributeMaxDynamicSharedMemorySize, kAtSmem2);

    // 1) split weights into bf16 hi/lo
    prep_w_kernel<<<256, 256>>>(Wi, Wo);
    // 2) gather f + pos into compact slot space
    gather_kernel<<<kNW1 + kNW2, 256>>>(feat, pos1, pos2, inds1, inds2);
    // 3) QK projection: QKp[:,0:128]=Q, [:,128:256]=K
    gemm_tc<<<dim3(kNTOK / kMT, 2), 256, kTcSmem>>>(
        QKin, Wh, Wl, 0, bi, QKp, 256, nullptr);
    // 4) V projection (token space)
    gemm_tc<<<dim3(kNTOK / kMT, 1), 256, kTcSmem>>>(
        feat, Wh, Wl, 256, bi + 256, Vp, 128, nullptr);
    // 5) windowed attention (tensor-core)
    attn_mma<kL1><<<kNW1, 256, kAtSmem1>>>(QKp, Vp, Obuf, s2t, 0);
    attn_mma<kL2><<<kNW2, 256, kAtSmem2>>>(QKp, Vp, Obuf, s2t, kN1);
    // 6) output projection with row scatter (bijective -> no init/atomics)
    gemm_tc<<<dim3(kNTOK / kMT, 1), 256, kTcSmem>>>(
        Obuf, Wh, Wl, 384, bo, out, 128, s2t);
}

// round 7
// speedup vs baseline: 3.3127x; 1.1534x over previous
#include <cuda_runtime.h>
#include <cuda_bf16.h>
#include <cstdint>

// ---------------- problem constants ----------------
constexpr int kD     = 128;
constexpr int kNH    = 8;
constexpr int kHD    = 16;
constexpr int kNW1   = 4096;
constexpr int kL1    = 36;
constexpr int kNW2   = 1024;
constexpr int kL2    = 100;
constexpr int kN1    = (kNW1 / 2) * (kL1 + kL1 / 2);   // 110592
constexpr int kN2    = (kNW2 / 2) * (kL2 + kL2 / 2);   // 76800
constexpr int kNTOK  = kN1 + kN2;                      // 187392 == 1464*128

static_assert(kNTOK % 128 == 0, "M tile");

extern __shared__ char smem_raw[];

// ---------------- device scratch ----------------
__device__ float g_QKin[(size_t)kNTOK * 128];
__device__ float g_QKp [(size_t)kNTOK * 256];
__device__ float g_Vp  [(size_t)kNTOK * 128];
__device__ float g_O   [(size_t)kNTOK * 128];
__device__ int   g_s2t [kNTOK];
__device__ __nv_bfloat16 g_Wh[512 * 128];   // rows 0..383 in_proj, 384..511 out_proj
__device__ __nv_bfloat16 g_Wl[512 * 128];

// ---------------- PTX helpers (sm_80+ generic) ----------------
__device__ __forceinline__ uint32_t smem_u32(const void* p) {
    uint32_t a;
    asm("{ .reg .u64 t; cvta.to.shared.u64 t, %1; cvt.u32.u64 %0, t; }"
        : "=r"(a) : "l"(p));
    return a;
}
__device__ __forceinline__ void cp_async16(uint32_t dst, const void* src) {
    asm volatile("cp.async.cg.shared.global [%0], [%1], 16;"
                 :: "r"(dst), "l"(src) : "memory");
}
__device__ __forceinline__ void cp_async_commit_wait() {
    asm volatile("cp.async.commit_group;" ::: "memory");
    asm volatile("cp.async.wait_group 0;" ::: "memory");
}
__device__ __forceinline__ void ldsm_x4(uint32_t* r, uint32_t a) {
    asm volatile("ldmatrix.sync.aligned.m8n8.x4.shared.b16 {%0,%1,%2,%3}, [%4];"
                 : "=r"(r[0]), "=r"(r[1]), "=r"(r[2]), "=r"(r[3]) : "r"(a));
}
__device__ __forceinline__ void ldsm_x2(uint32_t* r, uint32_t a) {
    asm volatile("ldmatrix.sync.aligned.m8n8.x2.shared.b16 {%0,%1}, [%2];"
                 : "=r"(r[0]), "=r"(r[1]) : "r"(a));
}
__device__ __forceinline__ void ldsm_x2_trans(uint32_t* r, uint32_t a) {
    asm volatile("ldmatrix.sync.aligned.m8n8.x2.trans.shared.b16 {%0,%1}, [%2];"
                 : "=r"(r[0]), "=r"(r[1]) : "r"(a));
}
__device__ __forceinline__ void mma_bf16(float* d, const uint32_t* a, const uint32_t* b) {
    asm volatile(
        "mma.sync.aligned.m16n8k16.row.col.f32.bf16.bf16.f32 "
        "{%0,%1,%2,%3}, {%4,%5,%6,%7}, {%8,%9}, {%0,%1,%2,%3};"
        : "+f"(d[0]), "+f"(d[1]), "+f"(d[2]), "+f"(d[3])
        : "r"(a[0]), "r"(a[1]), "r"(a[2]), "r"(a[3]), "r"(b[0]), "r"(b[1]));
}
__device__ __forceinline__ void pack_split(float x, float y, uint32_t& h, uint32_t& l) {
    __nv_bfloat162 hh = __floats2bfloat162_rn(x, y);
    __nv_bfloat162 ll = __floats2bfloat162_rn(x - __bfloat162float(hh.x),
                                              y - __bfloat162float(hh.y));
    h = *reinterpret_cast<uint32_t*>(&hh);
    l = *reinterpret_cast<uint32_t*>(&ll);
}
__device__ __forceinline__ void split_store(__nv_bfloat16* hi, __nv_bfloat16* lo,
                                            int idx, float4 v) {
    __nv_bfloat162 h01 = __floats2bfloat162_rn(v.x, v.y);
    __nv_bfloat162 h23 = __floats2bfloat162_rn(v.z, v.w);
    __nv_bfloat162 l01 = __floats2bfloat162_rn(v.x - __bfloat162float(h01.x),
                                               v.y - __bfloat162float(h01.y));
    __nv_bfloat162 l23 = __floats2bfloat162_rn(v.z - __bfloat162float(h23.x),
                                               v.w - __bfloat162float(h23.y));
    *reinterpret_cast<__nv_bfloat162*>(hi + idx)     = h01;
    *reinterpret_cast<__nv_bfloat162*>(hi + idx + 2) = h23;
    *reinterpret_cast<__nv_bfloat162*>(lo + idx)     = l01;
    *reinterpret_cast<__nv_bfloat162*>(lo + idx + 2) = l23;
}

// ---------------- weight prep ----------------
__global__ void prep_w_kernel(const float* __restrict__ Wi,
                              const float* __restrict__ Wo) {
    int t = blockIdx.x * 256 + threadIdx.x;
    if (t >= 512 * 128) return;
    float w = (t < 384 * 128) ? Wi[t] : Wo[t - 384 * 128];
    __nv_bfloat16 h = __float2bfloat16(w);
    __nv_bfloat16 l = __float2bfloat16(w - __bfloat162float(h));
    g_Wh[t] = h;
    g_Wl[t] = l;
}

// ---------------- gather ----------------
__global__ __launch_bounds__(256)
void gather_kernel(const float* __restrict__ feat,
                   const float* __restrict__ pos1,
                   const float* __restrict__ pos2,
                   const int* __restrict__ inds1,
                   const int* __restrict__ inds2) {
    int w = blockIdx.x;
    int Lv, slot0;
    const int* inds;
    const float* pos;
    if (w < kNW1) {
        Lv    = (w & 1) ? (kL1 / 2) : kL1;
        slot0 = (w >> 1) * (kL1 + kL1 / 2) + (w & 1) * kL1;
        inds  = inds1 + w * kL1;
        pos   = pos1 + (size_t)w * kL1 * 128;
    } else {
        int w2 = w - kNW1;
        Lv    = (w2 & 1) ? (kL2 / 2) : kL2;
        slot0 = kN1 + (w2 >> 1) * (kL2 + kL2 / 2) + (w2 & 1) * kL2;
        inds  = inds2 + w2 * kL2;
        pos   = pos2 + (size_t)w2 * kL2 * 128;
    }
    for (int t = threadIdx.x; t < Lv * 32; t += 256) {
        int l = t >> 5, c = t & 31;
        int tok = inds[l];
        float4 f = reinterpret_cast<const float4*>(feat + (size_t)tok * 128)[c];
        float4 p = reinterpret_cast<const float4*>(pos + (size_t)l * 128)[c];
        float4 r;
        r.x = f.x + p.x; r.y = f.y + p.y; r.z = f.z + p.z; r.w = f.w + p.w;
        reinterpret_cast<float4*>(g_QKin + (size_t)(slot0 + l) * 128)[c] = r;
        if (c == 0) g_s2t[slot0 + l] = tok;
    }
}

// ---------------- HMMA split-bf16 GEMM body (M-tile 64) ----------------
constexpr int kLds  = 136;
constexpr int kMT   = 64;
constexpr int kTcSmem = (2 * kMT + 2 * 128) * kLds * 2;   // 104448 B

__device__ __forceinline__ void gemm_body(
    const float* __restrict__ A, int brow,
    const float* __restrict__ bias,
    float* __restrict__ C, int ldc, int colbase,
    const int* __restrict__ s2t, int m0) {
    __nv_bfloat16* sAh = reinterpret_cast<__nv_bfloat16*>(smem_raw);
    __nv_bfloat16* sAl = sAh + kMT * kLds;
    __nv_bfloat16* sBh = sAh + 2 * kMT * kLds;
    __nv_bfloat16* sBl = sBh + 128 * kLds;

    const int tid = threadIdx.x;
    const int wid = tid >> 5, lane = tid & 31;

    // --- B via cp.async (no conversion needed), overlapped with A phase ---
    {
        int n = tid >> 1, ch = (tid & 1) * 64;
        const __nv_bfloat16* srcH = g_Wh + (size_t)(brow + n) * 128 + ch;
        const __nv_bfloat16* srcL = g_Wl + (size_t)(brow + n) * 128 + ch;
        uint32_t dstH = smem_u32(sBh + n * kLds + ch);
        uint32_t dstL = smem_u32(sBl + n * kLds + ch);
#pragma unroll
        for (int q = 0; q < 8; q++) {
            cp_async16(dstH + q * 16, srcH + q * 8);
            cp_async16(dstL + q * 16, srcL + q * 8);
        }
    }
    // --- A: LDG + fp32->bf16 hi/lo split + STS (overlaps the cp.async) ---
    {
        int r = tid >> 2, ch = (tid & 3) * 32;
        const float4* Ar = reinterpret_cast<const float4*>(A + (size_t)(m0 + r) * 128 + ch);
#pragma unroll
        for (int q = 0; q < 8; q++) {
            float4 v = Ar[q];
            split_store(sAh, sAl, r * kLds + ch + q * 4, v);
        }
    }
    cp_async_commit_wait();
    __syncthreads();

    const int wm = (wid & 1) * 32;
    const int wn = (wid >> 1) * 32;
    const uint32_t sAh_u = smem_u32(sAh);
    const uint32_t sBh_u = smem_u32(sBh);
    const uint32_t aLo = (uint32_t)(kMT * kLds * 2);
    const uint32_t bLo = (uint32_t)(128 * kLds * 2);

    const int aro = lane & 15;
    const int aco = (lane >> 4) * 8;
    const int bl  = lane & 15;
    const int bro = bl & 7;
    const int bco = ((bl >> 3) & 1) * 8;

    float acc[2][4][4];
#pragma unroll
    for (int mi = 0; mi < 2; mi++)
#pragma unroll
        for (int ni = 0; ni < 4; ni++)
#pragma unroll
            for (int j = 0; j < 4; j++) acc[mi][ni][j] = 0.f;

#pragma unroll
    for (int ks = 0; ks < 8; ks++) {
        uint32_t ah[2][4], al[2][4], bh[4][2], blo[4][2];
#pragma unroll
        for (int mi = 0; mi < 2; mi++) {
            uint32_t addr = sAh_u +
                (uint32_t)(((wm + mi * 16 + aro) * kLds + ks * 16 + aco) * 2);
            ldsm_x4(ah[mi], addr);
            ldsm_x4(al[mi], addr + aLo);
        }
#pragma unroll
        for (int ni = 0; ni < 4; ni++) {
            uint32_t addr = sBh_u +
                (uint32_t)(((wn + ni * 8 + bro) * kLds + ks * 16 + bco) * 2);
            ldsm_x2(bh[ni], addr);
            ldsm_x2(blo[ni], addr + bLo);
        }
#pragma unroll
        for (int mi = 0; mi < 2; mi++)
#pragma unroll
            for (int ni = 0; ni < 4; ni++) {
                mma_bf16(acc[mi][ni], ah[mi], bh[ni]);
                mma_bf16(acc[mi][ni], ah[mi], blo[ni]);
                mma_bf16(acc[mi][ni], al[mi], bh[ni]);
            }
    }

    const int g = lane >> 2, tig = lane & 3;
#pragma unroll
    for (int mi = 0; mi < 2; mi++) {
        int r0 = m0 + wm + mi * 16 + g;
        int r1 = r0 + 8;
        int or0 = s2t ? s2t[r0] : r0;
        int or1 = s2t ? s2t[r1] : r1;
#pragma unroll
        for (int ni = 0; ni < 4; ni++) {
            int col = wn + ni * 8 + 2 * tig;
            float b0 = bias[col];
            float b1 = bias[col + 1];
            *reinterpret_cast<float2*>(C + (size_t)or0 * ldc + colbase + col) =
                make_float2(acc[mi][ni][0] + b0, acc[mi][ni][1] + b1);
            *reinterpret_cast<float2*>(C + (size_t)or1 * ldc + colbase + col) =
                make_float2(acc[mi][ni][2] + b0, acc[mi][ni][3] + b1);
        }
    }
}

// fused Q/K/V projection: blockIdx.y = 0(Q),1(K),2(V)
__global__ __launch_bounds__(256)
void proj_fused(const float* __restrict__ QKin,
                const float* __restrict__ feat,
                const float* __restrict__ bi,
                float* __restrict__ QKp,
                float* __restrict__ Vp) {
    int nt = blockIdx.y;
    const float* A = (nt == 2) ? feat : QKin;
    float* C       = (nt == 2) ? Vp : QKp;
    int ldc        = (nt == 2) ? 128 : 256;
    int colbase    = (nt == 2) ? 0 : nt * 128;
    gemm_body(A, nt * 128, bi + nt * 128, C, ldc, colbase, nullptr,
              blockIdx.x * kMT);
}

// output projection with row scatter
__global__ __launch_bounds__(256)
void proj_out(const float* __restrict__ Obuf,
              const float* __restrict__ bo,
              float* __restrict__ out,
              const int* __restrict__ s2t) {
    gemm_body(Obuf, 384, bo, out, 128, 0, s2t, blockIdx.x * kMT);
}

// ---------------- MMA attention, compile-time window length ----------------
// One warp per head. S = (Q*0.25) K^T, softmax on fragments, O = P V.
template <int LV, int WPITCH>
__global__ __launch_bounds__(256)
void attn_mma(const float* __restrict__ QKp,
              const float* __restrict__ Vp,
              float* __restrict__ O,
              int slotbase, int slotoff) {
    constexpr int MT    = (LV + 15) / 16;
    constexpr int NT    = (LV + 7) / 8;
    constexpr int NTP   = (NT + 1) & ~1;
    constexpr int RowsP = ((LV + 15) / 16) * 16;
    constexpr int Lstr  = 136;
    constexpr int TSZ   = RowsP * Lstr;
    static_assert(NTP * 8 <= RowsP, "key pad fits");

    __nv_bfloat16* sQh = reinterpret_cast<__nv_bfloat16*>(smem_raw);
    __nv_bfloat16* sQl = sQh + TSZ;
    __nv_bfloat16* sKh = sQh + 2 * TSZ;
    __nv_bfloat16* sKl = sQh + 3 * TSZ;
    __nv_bfloat16* sVh = sQh + 4 * TSZ;
    __nv_bfloat16* sVl = sQh + 5 * TSZ;

    const int slot0 = slotbase + blockIdx.x * WPITCH + slotoff;
    const int tid = threadIdx.x;

    // --- fill smem: Q(scaled)/K/V hi+lo, zero pad rows ---
    for (int t = tid; t < RowsP * 32; t += 256) {
        int j = t >> 5, c = t & 31;
        int idx = j * Lstr + c * 4;
        if (j < LV) {
            int slot = slot0 + j;
            float4 q = reinterpret_cast<const float4*>(QKp + (size_t)slot * 256)[c];
            float4 k = reinterpret_cast<const float4*>(QKp + (size_t)slot * 256 + 128)[c];
            float4 v = reinterpret_cast<const float4*>(Vp + (size_t)g_s2t[slot] * 128)[c];
            q.x *= 0.25f; q.y *= 0.25f; q.z *= 0.25f; q.w *= 0.25f;
            split_store(sQh, sQl, idx, q);
            split_store(sKh, sKl, idx, k);
            split_store(sVh, sVl, idx, v);
        } else {
            uint2 z = make_uint2(0u, 0u);
            *reinterpret_cast<uint2*>(sQh + idx) = z;
            *reinterpret_cast<uint2*>(sQl + idx) = z;
            *reinterpret_cast<uint2*>(sKh + idx) = z;
            *reinterpret_cast<uint2*>(sKl + idx) = z;
            *reinterpret_cast<uint2*>(sVh + idx) = z;
            *reinterpret_cast<uint2*>(sVl + idx) = z;
        }
    }
    __syncthreads();

    const int warp = tid >> 5, lane = tid & 31;
    const int hb = warp * 16;
    const int T = lane >> 2, i4 = lane & 3;
    const int bl = lane & 15;

    const uint32_t uQh = smem_u32(sQh);
    const uint32_t uKh = smem_u32(sKh);
    const uint32_t uVh = smem_u32(sVh);
    const uint32_t LO  = (uint32_t)(TSZ * 2);

#pragma unroll
    for (int mi = 0; mi < MT; mi++) {
        uint32_t qh[4], ql[4];
        {
            int row = mi * 16 + (lane & 15);
            uint32_t a = uQh + (uint32_t)((row * Lstr + hb + (lane >> 4) * 8) * 2);
            ldsm_x4(qh, a);
            ldsm_x4(ql, a + LO);
        }

        float s[NTP][4];
        float m0 = -1e30f, m1 = -1e30f;
#pragma unroll
        for (int nj = 0; nj < NT; nj++) {
            uint32_t kh[2], kl[2];
            int row = nj * 8 + (bl & 7);
            uint32_t a = uKh + (uint32_t)((row * Lstr + hb + ((bl >> 3) & 1) * 8) * 2);
            ldsm_x2(kh, a);
            ldsm_x2(kl, a + LO);
            s[nj][0] = s[nj][1] = s[nj][2] = s[nj][3] = 0.f;
            mma_bf16(s[nj], qh, kh);
            mma_bf16(s[nj], qh, kl);
            mma_bf16(s[nj], ql, kh);
            if (nj * 8 + 7 >= LV) {     // boundary tile only (constexpr-foldable)
                int j0 = nj * 8 + 2 * i4;
                if (j0 >= LV)     { s[nj][0] = -1e30f; s[nj][2] = -1e30f; }
                if (j0 + 1 >= LV) { s[nj][1] = -1e30f; s[nj][3] = -1e30f; }
            }
            m0 = fmaxf(m0, fmaxf(s[nj][0], s[nj][1]));
            m1 = fmaxf(m1, fmaxf(s[nj][2], s[nj][3]));
        }
        m0 = fmaxf(m0, __shfl_xor_sync(0xffffffffu, m0, 1));
        m0 = fmaxf(m0, __shfl_xor_sync(0xffffffffu, m0, 2));
        m1 = fmaxf(m1, __shfl_xor_sync(0xffffffffu, m1, 1));
        m1 = fmaxf(m1, __shfl_xor_sync(0xffffffffu, m1, 2));

        float sum0 = 0.f, sum1 = 0.f;
#pragma unroll
        for (int nj = 0; nj < NT; nj++) {
            s[nj][0] = __expf(s[nj][0] - m0);
            s[nj][1] = __expf(s[nj][1] - m0);
            s[nj][2] = __expf(s[nj][2] - m1);
            s[nj][3] = __expf(s[nj][3] - m1);
            sum0 += s[nj][0] + s[nj][1];
            sum1 += s[nj][2] + s[nj][3];
        }
#pragma unroll
        for (int nj = NT; nj < NTP; nj++)
            s[nj][0] = s[nj][1] = s[nj][2] = s[nj][3] = 0.f;
        sum0 += __shfl_xor_sync(0xffffffffu, sum0, 1);
        sum0 += __shfl_xor_sync(0xffffffffu, sum0, 2);
        sum1 += __shfl_xor_sync(0xffffffffu, sum1, 1);
        sum1 += __shfl_xor_sync(0xffffffffu, sum1, 2);

        float o0[4] = {0.f, 0.f, 0.f, 0.f};
        float o1[4] = {0.f, 0.f, 0.f, 0.f};
#pragma unroll
        for (int kj = 0; kj < NTP / 2; kj++) {
            uint32_t ah[4], al[4];
            pack_split(s[2 * kj][0],     s[2 * kj][1],     ah[0], al[0]);
            pack_split(s[2 * kj][2],     s[2 * kj][3],     ah[1], al[1]);
            pack_split(s[2 * kj + 1][0], s[2 * kj + 1][1], ah[2], al[2]);
            pack_split(s[2 * kj + 1][2], s[2 * kj + 1][3], ah[3], al[3]);
            int row = kj * 16 + bl;
            uint32_t a0 = uVh + (uint32_t)((row * Lstr + hb) * 2);
            uint32_t vh[2], vl[2];
            ldsm_x2_trans(vh, a0);
            ldsm_x2_trans(vl, a0 + LO);
            mma_bf16(o0, ah, vh);
            mma_bf16(o0, ah, vl);
            mma_bf16(o0, al, vh);
            ldsm_x2_trans(vh, a0 + 16);
            ldsm_x2_trans(vl, a0 + 16 + LO);
            mma_bf16(o1, ah, vh);
            mma_bf16(o1, ah, vl);
            mma_bf16(o1, al, vh);
        }

        float inv0 = 1.f / sum0, inv1 = 1.f / sum1;
        int r0 = mi * 16 + T, r1 = r0 + 8;
        int col = hb + 2 * i4;
        if (r0 < LV) {
            float* p = O + (size_t)(slot0 + r0) * 128 + col;
            *reinterpret_cast<float2*>(p)     = make_float2(o0[0] * inv0, o0[1] * inv0);
            *reinterpret_cast<float2*>(p + 8) = make_float2(o1[0] * inv0, o1[1] * inv0);
        }
        if (r1 < LV) {
            float* p = O + (size_t)(slot0 + r1) * 128 + col;
            *reinterpret_cast<float2*>(p)     = make_float2(o0[2] * inv1, o0[3] * inv1);
            *reinterpret_cast<float2*>(p + 8) = make_float2(o1[2] * inv1, o1[3] * inv1);
        }
    }
}

// ---------------- launch ----------------
template <int LV>
constexpr int attn_smem() { return 6 * (((LV + 15) / 16) * 16) * 136 * 2; }

extern "C" void kernel_launch(void* const* d_in, const int* in_sizes, int n_in,
                              void* d_out, int out_size) {
    const float* feat  = (const float*)d_in[0];
    const float* pos1  = (const float*)d_in[1];
    const float* pos2  = (const float*)d_in[2];
    const float* Wi    = (const float*)d_in[3];
    const float* bi    = (const float*)d_in[4];
    const float* Wo    = (const float*)d_in[5];
    const float* bo    = (const float*)d_in[6];
    const int*   inds1 = (const int*)d_in[7];
    const int*   inds2 = (const int*)d_in[8];
    float* out = (float*)d_out;

    float *QKin, *QKp, *Vp, *Obuf;
    int* s2t;
    cudaGetSymbolAddress((void**)&QKin, g_QKin);
    cudaGetSymbolAddress((void**)&QKp,  g_QKp);
    cudaGetSymbolAddress((void**)&Vp,   g_Vp);
    cudaGetSymbolAddress((void**)&Obuf, g_O);
    cudaGetSymbolAddress((void**)&s2t,  g_s2t);

    cudaFuncSetAttribute(proj_fused, cudaFuncAttributeMaxDynamicSharedMemorySize, kTcSmem);
    cudaFuncSetAttribute(proj_out,   cudaFuncAttributeMaxDynamicSharedMemorySize, kTcSmem);
    cudaFuncSetAttribute((const void*)attn_mma<kL1, 54>,
                         cudaFuncAttributeMaxDynamicSharedMemorySize, attn_smem<kL1>());
    cudaFuncSetAttribute((const void*)attn_mma<kL1 / 2, 54>,
                         cudaFuncAttributeMaxDynamicSharedMemorySize, attn_smem<kL1 / 2>());
    cudaFuncSetAttribute((const void*)attn_mma<kL2, 150>,
                         cudaFuncAttributeMaxDynamicSharedMemorySize, attn_smem<kL2>());
    cudaFuncSetAttribute((const void*)attn_mma<kL2 / 2, 150>,
                         cudaFuncAttributeMaxDynamicSharedMemorySize, attn_smem<kL2 / 2>());

    // 1) split weights into bf16 hi/lo
    prep_w_kernel<<<256, 256>>>(Wi, Wo);
    // 2) gather f + pos into compact slot space
    gather_kernel<<<kNW1 + kNW2, 256>>>(feat, pos1, pos2, inds1, inds2);
    // 3) fused Q/K/V projections
    proj_fused<<<dim3(kNTOK / kMT, 3), 256, kTcSmem>>>(QKin, feat, bi, QKp, Vp);
    // 4) windowed attention (even/odd split, compile-time Lv)
    attn_mma<kL1, 54><<<kNW1 / 2, 256, attn_smem<kL1>()>>>(QKp, Vp, Obuf, 0, 0);
    attn_mma<kL1 / 2, 54><<<kNW1 / 2, 256, attn_smem<kL1 / 2>()>>>(QKp, Vp, Obuf, 0, kL1);
    attn_mma<kL2, 150><<<kNW2 / 2, 256, attn_smem<kL2>()>>>(QKp, Vp, Obuf, kN1, 0);
    attn_mma<kL2 / 2, 150><<<kNW2 / 2, 256, attn_smem<kL2 / 2>()>>>(QKp, Vp, Obuf, kN1, kL2);
    // 5) output projection with row scatter (bijective -> no init/atomics)
    proj_out<<<kNTOK / kMT, 256, kTcSmem>>>(Obuf, bo, out, s2t);
}

// round 8
// speedup vs baseline: 3.4833x; 1.0515x over previous
#include <cuda_runtime.h>
#include <cuda_bf16.h>
#include <cstdint>

// ---------------- problem constants ----------------
constexpr int kD     = 128;
constexpr int kNH    = 8;
constexpr int kHD    = 16;
constexpr int kNW1   = 4096;
constexpr int kL1    = 36;
constexpr int kNW2   = 1024;
constexpr int kL2    = 100;
constexpr int kN1    = (kNW1 / 2) * (kL1 + kL1 / 2);   // 110592
constexpr int kN2    = (kNW2 / 2) * (kL2 + kL2 / 2);   // 76800
constexpr int kNTOK  = kN1 + kN2;                      // 187392 == 1464*128

static_assert(kNTOK % 128 == 0, "M tile");

extern __shared__ char smem_raw[];

// ---------------- device scratch (all inter-stage data pre-split bf16) -----
__device__ __nv_bfloat16 g_QKih[(size_t)kNTOK * 128];
__device__ __nv_bfloat16 g_QKil[(size_t)kNTOK * 128];
__device__ __nv_bfloat16 g_QKph[(size_t)kNTOK * 256];
__device__ __nv_bfloat16 g_QKpl[(size_t)kNTOK * 256];
__device__ __nv_bfloat16 g_Vph [(size_t)kNTOK * 128];
__device__ __nv_bfloat16 g_Vpl [(size_t)kNTOK * 128];
__device__ __nv_bfloat16 g_Oh  [(size_t)kNTOK * 128];
__device__ __nv_bfloat16 g_Ol  [(size_t)kNTOK * 128];
__device__ int   g_s2t [kNTOK];
__device__ int   g_t2s [kNTOK];
__device__ float g_bias[512];
__device__ __nv_bfloat16 g_Wh[512 * 128];
__device__ __nv_bfloat16 g_Wl[512 * 128];

// ---------------- PTX helpers (sm_80+ generic) ----------------
__device__ __forceinline__ uint32_t smem_u32(const void* p) {
    uint32_t a;
    asm("{ .reg .u64 t; cvta.to.shared.u64 t, %1; cvt.u32.u64 %0, t; }"
        : "=r"(a) : "l"(p));
    return a;
}
__device__ __forceinline__ void cp_async16(uint32_t dst, const void* src) {
    asm volatile("cp.async.cg.shared.global [%0], [%1], 16;"
                 :: "r"(dst), "l"(src) : "memory");
}
__device__ __forceinline__ void cp_async_commit_wait() {
    asm volatile("cp.async.commit_group;" ::: "memory");
    asm volatile("cp.async.wait_group 0;" ::: "memory");
}
__device__ __forceinline__ void ldsm_x4(uint32_t* r, uint32_t a) {
    asm volatile("ldmatrix.sync.aligned.m8n8.x4.shared.b16 {%0,%1,%2,%3}, [%4];"
                 : "=r"(r[0]), "=r"(r[1]), "=r"(r[2]), "=r"(r[3]) : "r"(a));
}
__device__ __forceinline__ void ldsm_x2(uint32_t* r, uint32_t a) {
    asm volatile("ldmatrix.sync.aligned.m8n8.x2.shared.b16 {%0,%1}, [%2];"
                 : "=r"(r[0]), "=r"(r[1]) : "r"(a));
}
__device__ __forceinline__ void ldsm_x2_trans(uint32_t* r, uint32_t a) {
    asm volatile("ldmatrix.sync.aligned.m8n8.x2.trans.shared.b16 {%0,%1}, [%2];"
                 : "=r"(r[0]), "=r"(r[1]) : "r"(a));
}
__device__ __forceinline__ void mma_bf16(float* d, const uint32_t* a, const uint32_t* b) {
    asm volatile(
        "mma.sync.aligned.m16n8k16.row.col.f32.bf16.bf16.f32 "
        "{%0,%1,%2,%3}, {%4,%5,%6,%7}, {%8,%9}, {%0,%1,%2,%3};"
        : "+f"(d[0]), "+f"(d[1]), "+f"(d[2]), "+f"(d[3])
        : "r"(a[0]), "r"(a[1]), "r"(a[2]), "r"(a[3]), "r"(b[0]), "r"(b[1]));
}
__device__ __forceinline__ void pack_split(float x, float y, uint32_t& h, uint32_t& l) {
    __nv_bfloat162 hh = __floats2bfloat162_rn(x, y);
    __nv_bfloat162 ll = __floats2bfloat162_rn(x - __bfloat162float(hh.x),
                                              y - __bfloat162float(hh.y));
    h = *reinterpret_cast<uint32_t*>(&hh);
    l = *reinterpret_cast<uint32_t*>(&ll);
}
__device__ __forceinline__ void split_store(__nv_bfloat16* hi, __nv_bfloat16* lo,
                                            size_t idx, float4 v) {
    uint32_t h0, l0, h1, l1;
    pack_split(v.x, v.y, h0, l0);
    pack_split(v.z, v.w, h1, l1);
    *reinterpret_cast<uint2*>(hi + idx) = make_uint2(h0, h1);
    *reinterpret_cast<uint2*>(lo + idx) = make_uint2(l0, l1);
}

// ---------------- weight + bias prep (Q rows pre-scaled by 0.25) ----------
__global__ void prep_w_kernel(const float* __restrict__ Wi,
                              const float* __restrict__ Wo,
                              const float* __restrict__ bi,
                              const float* __restrict__ bo) {
    int t = blockIdx.x * 256 + threadIdx.x;
    if (t < 512) {
        float b = (t < 128) ? bi[t] * 0.25f : (t < 384 ? bi[t] : bo[t - 384]);
        g_bias[t] = b;
    }
    if (t >= 512 * 128) return;
    float w = (t < 384 * 128) ? Wi[t] : Wo[t - 384 * 128];
    if (t < 128 * 128) w *= 0.25f;   // fold score scale into Q
    __nv_bfloat16 h = __float2bfloat16(w);
    __nv_bfloat16 l = __float2bfloat16(w - __bfloat162float(h));
    g_Wh[t] = h;
    g_Wl[t] = l;
}

// ---------------- gather: split(feat[inds]+pos) -> QKi planes -------------
__global__ __launch_bounds__(256)
void gather_kernel(const float* __restrict__ feat,
                   const float* __restrict__ pos1,
                   const float* __restrict__ pos2,
                   const int* __restrict__ inds1,
                   const int* __restrict__ inds2) {
    int w = blockIdx.x;
    int Lv, slot0;
    const int* inds;
    const float* pos;
    if (w < kNW1) {
        Lv    = (w & 1) ? (kL1 / 2) : kL1;
        slot0 = (w >> 1) * (kL1 + kL1 / 2) + (w & 1) * kL1;
        inds  = inds1 + w * kL1;
        pos   = pos1 + (size_t)w * kL1 * 128;
    } else {
        int w2 = w - kNW1;
        Lv    = (w2 & 1) ? (kL2 / 2) : kL2;
        slot0 = kN1 + (w2 >> 1) * (kL2 + kL2 / 2) + (w2 & 1) * kL2;
        inds  = inds2 + w2 * kL2;
        pos   = pos2 + (size_t)w2 * kL2 * 128;
    }
    for (int t = threadIdx.x; t < Lv * 32; t += 256) {
        int l = t >> 5, c = t & 31;
        int tok = inds[l];
        float4 f = reinterpret_cast<const float4*>(feat + (size_t)tok * 128)[c];
        float4 p = reinterpret_cast<const float4*>(pos + (size_t)l * 128)[c];
        float4 r;
        r.x = f.x + p.x; r.y = f.y + p.y; r.z = f.z + p.z; r.w = f.w + p.w;
        split_store(g_QKih, g_QKil, (size_t)(slot0 + l) * 128 + c * 4, r);
        if (c == 0) {
            g_s2t[slot0 + l] = tok;
            g_t2s[tok] = slot0 + l;
        }
    }
}

// ---------------- HMMA split-bf16 GEMM body (M-tile 64) ----------------
constexpr int kLds  = 136;
constexpr int kMT   = 64;
constexpr int kTcSmem = (2 * kMT + 2 * 128) * kLds * 2;   // 104448 B

// ASPLIT: A supplied as pre-split bf16 planes (pure cp.async load).
// OUTF32: write fp32 (final output) instead of split bf16 planes.
template <bool ASPLIT, bool OUTF32>
__device__ __forceinline__ void gemm_body(
    const __nv_bfloat16* __restrict__ Ah, const __nv_bfloat16* __restrict__ Al,
    const float* __restrict__ Af,
    int brow, const float* __restrict__ bias,
    __nv_bfloat16* __restrict__ outH, __nv_bfloat16* __restrict__ outL,
    float* __restrict__ outF,
    int ldc, int colbase, const int* __restrict__ rowmap, int m0) {
    __nv_bfloat16* sAh = reinterpret_cast<__nv_bfloat16*>(smem_raw);
    __nv_bfloat16* sAl = sAh + kMT * kLds;
    __nv_bfloat16* sBh = sAh + 2 * kMT * kLds;
    __nv_bfloat16* sBl = sBh + 128 * kLds;

    const int tid = threadIdx.x;
    const int wid = tid >> 5, lane = tid & 31;

    // --- B via cp.async (both planes) ---
    {
        int n = tid >> 1, ch = (tid & 1) * 64;
        const __nv_bfloat16* srcH = g_Wh + (size_t)(brow + n) * 128 + ch;
        const __nv_bfloat16* srcL = g_Wl + (size_t)(brow + n) * 128 + ch;
        uint32_t dstH = smem_u32(sBh + n * kLds + ch);
        uint32_t dstL = smem_u32(sBl + n * kLds + ch);
#pragma unroll
        for (int q = 0; q < 8; q++) {
            cp_async16(dstH + q * 16, srcH + q * 8);
            cp_async16(dstL + q * 16, srcL + q * 8);
        }
    }
    // --- A ---
    if (ASPLIT) {
        int r = tid >> 2, c0 = (tid & 3) * 4;           // 4 chunks of 16B
        const __nv_bfloat16* srcH = Ah + (size_t)(m0 + r) * 128 + c0 * 8;
        const __nv_bfloat16* srcL = Al + (size_t)(m0 + r) * 128 + c0 * 8;
        uint32_t dstH = smem_u32(sAh + r * kLds + c0 * 8);
        uint32_t dstL = smem_u32(sAl + r * kLds + c0 * 8);
#pragma unroll
        for (int q = 0; q < 4; q++) {
            cp_async16(dstH + q * 16, srcH + q * 8);
            cp_async16(dstL + q * 16, srcL + q * 8);
        }
    } else {
        int r = tid >> 2, ch = (tid & 3) * 32;
        const float4* Ar = reinterpret_cast<const float4*>(Af + (size_t)(m0 + r) * 128 + ch);
#pragma unroll
        for (int q = 0; q < 8; q++) {
            float4 v = Ar[q];
            split_store(sAh, sAl, (size_t)(r * kLds + ch + q * 4), v);
        }
    }
    cp_async_commit_wait();
    __syncthreads();

    const int wm = (wid & 1) * 32;
    const int wn = (wid >> 1) * 32;
    const uint32_t sAh_u = smem_u32(sAh);
    const uint32_t sBh_u = smem_u32(sBh);
    const uint32_t aLo = (uint32_t)(kMT * kLds * 2);
    const uint32_t bLo = (uint32_t)(128 * kLds * 2);

    const int aro = lane & 15;
    const int aco = (lane >> 4) * 8;
    const int bl  = lane & 15;
    const int bro = bl & 7;
    const int bco = ((bl >> 3) & 1) * 8;

    float acc[2][4][4];
#pragma unroll
    for (int mi = 0; mi < 2; mi++)
#pragma unroll
        for (int ni = 0; ni < 4; ni++)
#pragma unroll
            for (int j = 0; j < 4; j++) acc[mi][ni][j] = 0.f;

#pragma unroll
    for (int ks = 0; ks < 8; ks++) {
        uint32_t ah[2][4], al[2][4], bh[4][2], blo[4][2];
#pragma unroll
        for (int mi = 0; mi < 2; mi++) {
            uint32_t addr = sAh_u +
                (uint32_t)(((wm + mi * 16 + aro) * kLds + ks * 16 + aco) * 2);
            ldsm_x4(ah[mi], addr);
            ldsm_x4(al[mi], addr + aLo);
        }
#pragma unroll
        for (int ni = 0; ni < 4; ni++) {
            uint32_t addr = sBh_u +
                (uint32_t)(((wn + ni * 8 + bro) * kLds + ks * 16 + bco) * 2);
            ldsm_x2(bh[ni], addr);
            ldsm_x2(blo[ni], addr + bLo);
        }
#pragma unroll
        for (int mi = 0; mi < 2; mi++)
#pragma unroll
            for (int ni = 0; ni < 4; ni++) {
                mma_bf16(acc[mi][ni], ah[mi], bh[ni]);
                mma_bf16(acc[mi][ni], ah[mi], blo[ni]);
                mma_bf16(acc[mi][ni], al[mi], bh[ni]);
            }
    }

    const int g = lane >> 2, tig = lane & 3;
#pragma unroll
    for (int mi = 0; mi < 2; mi++) {
        int r0 = m0 + wm + mi * 16 + g;
        int r1 = r0 + 8;
        int or0 = rowmap ? rowmap[r0] : r0;
        int or1 = rowmap ? rowmap[r1] : r1;
#pragma unroll
        for (int ni = 0; ni < 4; ni++) {
            int col = wn + ni * 8 + 2 * tig;
            float b0 = bias[col];
            float b1 = bias[col + 1];
            float v00 = acc[mi][ni][0] + b0, v01 = acc[mi][ni][1] + b1;
            float v10 = acc[mi][ni][2] + b0, v11 = acc[mi][ni][3] + b1;
            if (OUTF32) {
                *reinterpret_cast<float2*>(outF + (size_t)or0 * ldc + colbase + col) =
                    make_float2(v00, v01);
                *reinterpret_cast<float2*>(outF + (size_t)or1 * ldc + colbase + col) =
                    make_float2(v10, v11);
            } else {
                uint32_t h, l;
                pack_split(v00, v01, h, l);
                *reinterpret_cast<uint32_t*>(outH + (size_t)or0 * ldc + colbase + col) = h;
                *reinterpret_cast<uint32_t*>(outL + (size_t)or0 * ldc + colbase + col) = l;
                pack_split(v10, v11, h, l);
                *reinterpret_cast<uint32_t*>(outH + (size_t)or1 * ldc + colbase + col) = h;
                *reinterpret_cast<uint32_t*>(outL + (size_t)or1 * ldc + colbase + col) = l;
            }
        }
    }
}

// QK projection (A = split QKi planes, out = split QKp planes)
__global__ __launch_bounds__(256)
void proj_qk() {
    int nt = blockIdx.y;
    gemm_body<true, false>(g_QKih, g_QKil, nullptr, nt * 128, g_bias + nt * 128,
                           g_QKph, g_QKpl, nullptr, 256, nt * 128, nullptr,
                           blockIdx.x * kMT);
}
// V projection (A = fp32 feat token-order, out scattered to slot order)
__global__ __launch_bounds__(256)
void proj_v(const float* __restrict__ feat) {
    gemm_body<false, false>(nullptr, nullptr, feat, 256, g_bias + 256,
                            g_Vph, g_Vpl, nullptr, 128, 0, g_t2s,
                            blockIdx.x * kMT);
}
// output projection (A = split O planes, out fp32 scattered to token order)
__global__ __launch_bounds__(256)
void proj_out(float* __restrict__ out) {
    gemm_body<true, true>(g_Oh, g_Ol, nullptr, 384, g_bias + 384,
                          nullptr, nullptr, out, 128, 0, g_s2t,
                          blockIdx.x * kMT);
}

// ---------------- MMA attention: pure cp.async fill, one warp per head ----
template <int LV, int WPITCH>
__global__ __launch_bounds__(256)
void attn_mma(int slotbase, int slotoff) {
    constexpr int MT    = (LV + 15) / 16;
    constexpr int NT    = (LV + 7) / 8;
    constexpr int NTP   = (NT + 1) & ~1;
    constexpr int RowsP = ((LV + 15) / 16) * 16;
    constexpr int Lstr  = 136;
    constexpr int TSZ   = RowsP * Lstr;
    static_assert(NTP * 8 <= RowsP, "key pad fits");

    __nv_bfloat16* sQh = reinterpret_cast<__nv_bfloat16*>(smem_raw);
    __nv_bfloat16* sQl = sQh + TSZ;
    __nv_bfloat16* sKh = sQh + 2 * TSZ;
    __nv_bfloat16* sKl = sQh + 3 * TSZ;
    __nv_bfloat16* sVh = sQh + 4 * TSZ;
    __nv_bfloat16* sVl = sQh + 5 * TSZ;

    const int slot0 = slotbase + blockIdx.x * WPITCH + slotoff;
    const int tid = threadIdx.x;

    // --- fill: 16B chunks, 6 planes; all cp.async, zero pad rows ---
    for (int t = tid; t < RowsP * 16; t += 256) {
        int j = t >> 4, c = t & 15;
        uint32_t off = (uint32_t)(j * Lstr * 2 + c * 16);
        if (j < LV) {
            size_t qk = (size_t)(slot0 + j) * 256 + c * 8;
            size_t vv = (size_t)(slot0 + j) * 128 + c * 8;
            cp_async16(smem_u32(sQh) + off, g_QKph + qk);
            cp_async16(smem_u32(sQl) + off, g_QKpl + qk);
            cp_async16(smem_u32(sKh) + off, g_QKph + qk + 128);
            cp_async16(smem_u32(sKl) + off, g_QKpl + qk + 128);
            cp_async16(smem_u32(sVh) + off, g_Vph + vv);
            cp_async16(smem_u32(sVl) + off, g_Vpl + vv);
        } else {
            uint4 z = make_uint4(0u, 0u, 0u, 0u);
            *reinterpret_cast<uint4*>(reinterpret_cast<char*>(sQh) + off) = z;
            *reinterpret_cast<uint4*>(reinterpret_cast<char*>(sQl) + off) = z;
            *reinterpret_cast<uint4*>(reinterpret_cast<char*>(sKh) + off) = z;
            *reinterpret_cast<uint4*>(reinterpret_cast<char*>(sKl) + off) = z;
            *reinterpret_cast<uint4*>(reinterpret_cast<char*>(sVh) + off) = z;
            *reinterpret_cast<uint4*>(reinterpret_cast<char*>(sVl) + off) = z;
        }
    }
    cp_async_commit_wait();
    __syncthreads();

    const int warp = tid >> 5, lane = tid & 31;
    const int hb = warp * 16;
    const int T = lane >> 2, i4 = lane & 3;
    const int bl = lane & 15;

    const uint32_t uQh = smem_u32(sQh);
    const uint32_t uKh = smem_u32(sKh);
    const uint32_t uVh = smem_u32(sVh);
    const uint32_t LO  = (uint32_t)(TSZ * 2);

#pragma unroll
    for (int mi = 0; mi < MT; mi++) {
        uint32_t qh[4], ql[4];
        {
            int row = mi * 16 + (lane & 15);
            uint32_t a = uQh + (uint32_t)((row * Lstr + hb + (lane >> 4) * 8) * 2);
            ldsm_x4(qh, a);
            ldsm_x4(ql, a + LO);
        }

        float s[NTP][4];
        float m0 = -1e30f, m1 = -1e30f;
#pragma unroll
        for (int nj = 0; nj < NT; nj++) {
            uint32_t kh[2], kl[2];
            int row = nj * 8 + (bl & 7);
            uint32_t a = uKh + (uint32_t)((row * Lstr + hb + ((bl >> 3) & 1) * 8) * 2);
            ldsm_x2(kh, a);
            ldsm_x2(kl, a + LO);
            s[nj][0] = s[nj][1] = s[nj][2] = s[nj][3] = 0.f;
            mma_bf16(s[nj], qh, kh);
            mma_bf16(s[nj], qh, kl);
            mma_bf16(s[nj], ql, kh);
            if (nj * 8 + 7 >= LV) {
                int j0 = nj * 8 + 2 * i4;
                if (j0 >= LV)     { s[nj][0] = -1e30f; s[nj][2] = -1e30f; }
                if (j0 + 1 >= LV) { s[nj][1] = -1e30f; s[nj][3] = -1e30f; }
            }
            m0 = fmaxf(m0, fmaxf(s[nj][0], s[nj][1]));
            m1 = fmaxf(m1, fmaxf(s[nj][2], s[nj][3]));
        }
        m0 = fmaxf(m0, __shfl_xor_sync(0xffffffffu, m0, 1));
        m0 = fmaxf(m0, __shfl_xor_sync(0xffffffffu, m0, 2));
        m1 = fmaxf(m1, __shfl_xor_sync(0xffffffffu, m1, 1));
        m1 = fmaxf(m1, __shfl_xor_sync(0xffffffffu, m1, 2));

        float sum0 = 0.f, sum1 = 0.f;
#pragma unroll
        for (int nj = 0; nj < NT; nj++) {
            s[nj][0] = __expf(s[nj][0] - m0);
            s[nj][1] = __expf(s[nj][1] - m0);
            s[nj][2] = __expf(s[nj][2] - m1);
            s[nj][3] = __expf(s[nj][3] - m1);
            sum0 += s[nj][0] + s[nj][1];
            sum1 += s[nj][2] + s[nj][3];
        }
#pragma unroll
        for (int nj = NT; nj < NTP; nj++)
            s[nj][0] = s[nj][1] = s[nj][2] = s[nj][3] = 0.f;
        sum0 += __shfl_xor_sync(0xffffffffu, sum0, 1);
        sum0 += __shfl_xor_sync(0xffffffffu, sum0, 2);
        sum1 += __shfl_xor_sync(0xffffffffu, sum1, 1);
        sum1 += __shfl_xor_sync(0xffffffffu, sum1, 2);

        float o0[4] = {0.f, 0.f, 0.f, 0.f};
        float o1[4] = {0.f, 0.f, 0.f, 0.f};
#pragma unroll
        for (int kj = 0; kj < NTP / 2; kj++) {
            uint32_t ah[4], al[4];
            pack_split(s[2 * kj][0],     s[2 * kj][1],     ah[0], al[0]);
            pack_split(s[2 * kj][2],     s[2 * kj][3],     ah[1], al[1]);
            pack_split(s[2 * kj + 1][0], s[2 * kj + 1][1], ah[2], al[2]);
            pack_split(s[2 * kj + 1][2], s[2 * kj + 1][3], ah[3], al[3]);
            int row = kj * 16 + bl;
            uint32_t a0 = uVh + (uint32_t)((row * Lstr + hb) * 2);
            uint32_t vh[2], vl[2];
            ldsm_x2_trans(vh, a0);
            ldsm_x2_trans(vl, a0 + LO);
            mma_bf16(o0, ah, vh);
            mma_bf16(o0, ah, vl);
            mma_bf16(o0, al, vh);
            ldsm_x2_trans(vh, a0 + 16);
            ldsm_x2_trans(vl, a0 + 16 + LO);
            mma_bf16(o1, ah, vh);
            mma_bf16(o1, ah, vl);
            mma_bf16(o1, al, vh);
        }

        float inv0 = 1.f / sum0, inv1 = 1.f / sum1;
        int r0 = mi * 16 + T, r1 = r0 + 8;
        int col = hb + 2 * i4;
        if (r0 < LV) {
            size_t base = (size_t)(slot0 + r0) * 128 + col;
            uint32_t h, l;
            pack_split(o0[0] * inv0, o0[1] * inv0, h, l);
            *reinterpret_cast<uint32_t*>(g_Oh + base) = h;
            *reinterpret_cast<uint32_t*>(g_Ol + base) = l;
            pack_split(o1[0] * inv0, o1[1] * inv0, h, l);
            *reinterpret_cast<uint32_t*>(g_Oh + base + 8) = h;
            *reinterpret_cast<uint32_t*>(g_Ol + base + 8) = l;
        }
        if (r1 < LV) {
            size_t base = (size_t)(slot0 + r1) * 128 + col;
            uint32_t h, l;
            pack_split(o0[2] * inv1, o0[3] * inv1, h, l);
            *reinterpret_cast<uint32_t*>(g_Oh + base) = h;
            *reinterpret_cast<uint32_t*>(g_Ol + base) = l;
            pack_split(o1[2] * inv1, o1[3] * inv1, h, l);
            *reinterpret_cast<uint32_t*>(g_Oh + base + 8) = h;
            *reinterpret_cast<uint32_t*>(g_Ol + base + 8) = l;
        }
    }
}

// ---------------- launch ----------------
template <int LV>
constexpr int attn_smem() { return 6 * (((LV + 15) / 16) * 16) * 136 * 2; }

extern "C" void kernel_launch(void* const* d_in, const int* in_sizes, int n_in,
                              void* d_out, int out_size) {
    const float* feat  = (const float*)d_in[0];
    const float* pos1  = (const float*)d_in[1];
    const float* pos2  = (const float*)d_in[2];
    const float* Wi    = (const float*)d_in[3];
    const float* bi    = (const float*)d_in[4];
    const float* Wo    = (const float*)d_in[5];
    const float* bo    = (const float*)d_in[6];
    const int*   inds1 = (const int*)d_in[7];
    const int*   inds2 = (const int*)d_in[8];
    float* out = (float*)d_out;

    cudaFuncSetAttribute(proj_qk,  cudaFuncAttributeMaxDynamicSharedMemorySize, kTcSmem);
    cudaFuncSetAttribute(proj_v,   cudaFuncAttributeMaxDynamicSharedMemorySize, kTcSmem);
    cudaFuncSetAttribute(proj_out, cudaFuncAttributeMaxDynamicSharedMemorySize, kTcSmem);
    cudaFuncSetAttribute((const void*)attn_mma<kL1, 54>,
                         cudaFuncAttributeMaxDynamicSharedMemorySize, attn_smem<kL1>());
    cudaFuncSetAttribute((const void*)attn_mma<kL1 / 2, 54>,
                         cudaFuncAttributeMaxDynamicSharedMemorySize, attn_smem<kL1 / 2>());
    cudaFuncSetAttribute((const void*)attn_mma<kL2, 150>,
                         cudaFuncAttributeMaxDynamicSharedMemorySize, attn_smem<kL2>());
    cudaFuncSetAttribute((const void*)attn_mma<kL2 / 2, 150>,
                         cudaFuncAttributeMaxDynamicSharedMemorySize, attn_smem<kL2 / 2>());

    // 1) weights + bias (Q pre-scaled) into bf16 hi/lo
    prep_w_kernel<<<256, 256>>>(Wi, Wo, bi, bo);
    // 2) gather: split(feat+pos) into slot space + s2t/t2s maps
    gather_kernel<<<kNW1 + kNW2, 256>>>(feat, pos1, pos2, inds1, inds2);
    // 3) projections
    proj_qk<<<dim3(kNTOK / kMT, 2), 256, kTcSmem>>>();
    proj_v<<<kNTOK / kMT, 256, kTcSmem>>>(feat);
    // 4) windowed attention (even/odd split, compile-time Lv)
    attn_mma<kL1, 54><<<kNW1 / 2, 256, attn_smem<kL1>()>>>(0, 0);
    attn_mma<kL1 / 2, 54><<<kNW1 / 2, 256, attn_smem<kL1 / 2>()>>>(0, kL1);
    attn_mma<kL2, 150><<<kNW2 / 2, 256, attn_smem<kL2>()>>>(kN1, 0);
    attn_mma<kL2 / 2, 150><<<kNW2 / 2, 256, attn_smem<kL2 / 2>()>>>(kN1, kL2);
    // 5) output projection with row scatter (bijective -> no init/atomics)
    proj_out<<<kNTOK / kMT, 256, kTcSmem>>>(out);
}

// round 9
// speedup vs baseline: 4.1651x; 1.1957x over previous
#include <cuda_runtime.h>
#include <cuda_bf16.h>
#include <cstdint>

// ---------------- problem constants ----------------
constexpr int kD     = 128;
constexpr int kNH    = 8;
constexpr int kHD    = 16;
constexpr int kNW1   = 4096;
constexpr int kL1    = 36;
constexpr int kNW2   = 1024;
constexpr int kL2    = 100;
constexpr int kN1    = (kNW1 / 2) * (kL1 + kL1 / 2);   // 110592
constexpr int kN2    = (kNW2 / 2) * (kL2 + kL2 / 2);   // 76800
constexpr int kNTOK  = kN1 + kN2;                      // 187392 == 1464*128

static_assert(kNTOK % 128 == 0, "M tile");

extern __shared__ char smem_raw[];

// ---------------- device scratch (all inter-stage data pre-split bf16) -----
__device__ __nv_bfloat16 g_QKih[(size_t)kNTOK * 128];
__device__ __nv_bfloat16 g_QKil[(size_t)kNTOK * 128];
__device__ __nv_bfloat16 g_Fh  [(size_t)kNTOK * 128];   // feat, slot order
__device__ __nv_bfloat16 g_Fl  [(size_t)kNTOK * 128];
__device__ __nv_bfloat16 g_QKph[(size_t)kNTOK * 256];
__device__ __nv_bfloat16 g_QKpl[(size_t)kNTOK * 256];
__device__ __nv_bfloat16 g_Vph [(size_t)kNTOK * 128];
__device__ __nv_bfloat16 g_Vpl [(size_t)kNTOK * 128];
__device__ __nv_bfloat16 g_Oh  [(size_t)kNTOK * 128];
__device__ __nv_bfloat16 g_Ol  [(size_t)kNTOK * 128];
__device__ int   g_s2t [kNTOK];
__device__ float g_bias[512];
__device__ __nv_bfloat16 g_Wh[512 * 128];
__device__ __nv_bfloat16 g_Wl[512 * 128];

// ---------------- PTX helpers (sm_80+ generic) ----------------
__device__ __forceinline__ uint32_t smem_u32(const void* p) {
    uint32_t a;
    asm("{ .reg .u64 t; cvta.to.shared.u64 t, %1; cvt.u32.u64 %0, t; }"
        : "=r"(a) : "l"(p));
    return a;
}
__device__ __forceinline__ void cp_async16(uint32_t dst, const void* src) {
    asm volatile("cp.async.cg.shared.global [%0], [%1], 16;"
                 :: "r"(dst), "l"(src) : "memory");
}
__device__ __forceinline__ void cp_async_commit_wait() {
    asm volatile("cp.async.commit_group;" ::: "memory");
    asm volatile("cp.async.wait_group 0;" ::: "memory");
}
__device__ __forceinline__ void ldsm_x4(uint32_t* r, uint32_t a) {
    asm volatile("ldmatrix.sync.aligned.m8n8.x4.shared.b16 {%0,%1,%2,%3}, [%4];"
                 : "=r"(r[0]), "=r"(r[1]), "=r"(r[2]), "=r"(r[3]) : "r"(a));
}
__device__ __forceinline__ void ldsm_x2(uint32_t* r, uint32_t a) {
    asm volatile("ldmatrix.sync.aligned.m8n8.x2.shared.b16 {%0,%1}, [%2];"
                 : "=r"(r[0]), "=r"(r[1]) : "r"(a));
}
__device__ __forceinline__ void ldsm_x2_trans(uint32_t* r, uint32_t a) {
    asm volatile("ldmatrix.sync.aligned.m8n8.x2.trans.shared.b16 {%0,%1}, [%2];"
                 : "=r"(r[0]), "=r"(r[1]) : "r"(a));
}
__device__ __forceinline__ void mma_bf16(float* d, const uint32_t* a, const uint32_t* b) {
    asm volatile(
        "mma.sync.aligned.m16n8k16.row.col.f32.bf16.bf16.f32 "
        "{%0,%1,%2,%3}, {%4,%5,%6,%7}, {%8,%9}, {%0,%1,%2,%3};"
        : "+f"(d[0]), "+f"(d[1]), "+f"(d[2]), "+f"(d[3])
        : "r"(a[0]), "r"(a[1]), "r"(a[2]), "r"(a[3]), "r"(b[0]), "r"(b[1]));
}
__device__ __forceinline__ void pack_split(float x, float y, uint32_t& h, uint32_t& l) {
    __nv_bfloat162 hh = __floats2bfloat162_rn(x, y);
    __nv_bfloat162 ll = __floats2bfloat162_rn(x - __bfloat162float(hh.x),
                                              y - __bfloat162float(hh.y));
    h = *reinterpret_cast<uint32_t*>(&hh);
    l = *reinterpret_cast<uint32_t*>(&ll);
}
__device__ __forceinline__ void split_store(__nv_bfloat16* hi, __nv_bfloat16* lo,
                                            size_t idx, float4 v) {
    uint32_t h0, l0, h1, l1;
    pack_split(v.x, v.y, h0, l0);
    pack_split(v.z, v.w, h1, l1);
    *reinterpret_cast<uint2*>(hi + idx) = make_uint2(h0, h1);
    *reinterpret_cast<uint2*>(lo + idx) = make_uint2(l0, l1);
}

// ---------------- weight + bias prep (Q rows pre-scaled by 0.25) ----------
__global__ void prep_w_kernel(const float* __restrict__ Wi,
                              const float* __restrict__ Wo,
                              const float* __restrict__ bi,
                              const float* __restrict__ bo) {
    int t = blockIdx.x * 256 + threadIdx.x;
    if (t < 512) {
        float b = (t < 128) ? bi[t] * 0.25f : (t < 384 ? bi[t] : bo[t - 384]);
        g_bias[t] = b;
    }
    if (t >= 512 * 128) return;
    float w = (t < 384 * 128) ? Wi[t] : Wo[t - 384 * 128];
    if (t < 128 * 128) w *= 0.25f;   // fold score scale into Q
    __nv_bfloat16 h = __float2bfloat16(w);
    __nv_bfloat16 l = __float2bfloat16(w - __bfloat162float(h));
    g_Wh[t] = h;
    g_Wl[t] = l;
}

// ---------------- gather: split(feat+pos) and split(feat) -> slot planes --
__global__ __launch_bounds__(256)
void gather_kernel(const float* __restrict__ feat,
                   const float* __restrict__ pos1,
                   const float* __restrict__ pos2,
                   const int* __restrict__ inds1,
                   const int* __restrict__ inds2) {
    int w = blockIdx.x;
    int Lv, slot0;
    const int* inds;
    const float* pos;
    if (w < kNW1) {
        Lv    = (w & 1) ? (kL1 / 2) : kL1;
        slot0 = (w >> 1) * (kL1 + kL1 / 2) + (w & 1) * kL1;
        inds  = inds1 + w * kL1;
        pos   = pos1 + (size_t)w * kL1 * 128;
    } else {
        int w2 = w - kNW1;
        Lv    = (w2 & 1) ? (kL2 / 2) : kL2;
        slot0 = kN1 + (w2 >> 1) * (kL2 + kL2 / 2) + (w2 & 1) * kL2;
        inds  = inds2 + w2 * kL2;
        pos   = pos2 + (size_t)w2 * kL2 * 128;
    }
    for (int t = threadIdx.x; t < Lv * 32; t += 256) {
        int l = t >> 5, c = t & 31;
        int tok = inds[l];
        float4 f = reinterpret_cast<const float4*>(feat + (size_t)tok * 128)[c];
        float4 p = reinterpret_cast<const float4*>(pos + (size_t)l * 128)[c];
        float4 r;
        r.x = f.x + p.x; r.y = f.y + p.y; r.z = f.z + p.z; r.w = f.w + p.w;
        size_t idx = (size_t)(slot0 + l) * 128 + c * 4;
        split_store(g_QKih, g_QKil, idx, r);
        split_store(g_Fh, g_Fl, idx, f);
        if (c == 0) g_s2t[slot0 + l] = tok;
    }
}

// ---------------- multi-tile HMMA GEMM, B resident, A reg-prefetch --------
constexpr int kLds  = 136;
constexpr int kMT   = 64;
constexpr int kTPB  = 8;                                  // M-tiles per block
constexpr int kGrdX = kNTOK / kMT / kTPB;                 // 366
constexpr int kTcSmem = (2 * kMT + 2 * 128) * kLds * 2;   // 104448 B
static_assert(kNTOK % (kMT * kTPB) == 0, "tile grid");

template <bool OUTF32>
__device__ __forceinline__ void gemm_multi(
    const __nv_bfloat16* __restrict__ Ah, const __nv_bfloat16* __restrict__ Al,
    int brow, const float* __restrict__ bias,
    __nv_bfloat16* __restrict__ outH, __nv_bfloat16* __restrict__ outL,
    float* __restrict__ outF,
    int ldc, int colbase, const int* __restrict__ rowmap, int tile0) {
    __nv_bfloat16* sAh = reinterpret_cast<__nv_bfloat16*>(smem_raw);
    __nv_bfloat16* sAl = sAh + kMT * kLds;
    __nv_bfloat16* sBh = sAh + 2 * kMT * kLds;
    __nv_bfloat16* sBl = sBh + 128 * kLds;

    const int tid = threadIdx.x;
    const int wid = tid >> 5, lane = tid & 31;
    const int r  = tid >> 2;              // A row 0..63
    const int ch = (tid & 3) * 32;        // A col chunk (32 cols = 64B)

    // --- B resident load (once) + A tile0 via cp.async ---
    {
        int n = tid >> 1, bch = (tid & 1) * 64;
        const __nv_bfloat16* srcH = g_Wh + (size_t)(brow + n) * 128 + bch;
        const __nv_bfloat16* srcL = g_Wl + (size_t)(brow + n) * 128 + bch;
        uint32_t dstH = smem_u32(sBh + n * kLds + bch);
        uint32_t dstL = smem_u32(sBl + n * kLds + bch);
#pragma unroll
        for (int q = 0; q < 8; q++) {
            cp_async16(dstH + q * 16, srcH + q * 8);
            cp_async16(dstL + q * 16, srcL + q * 8);
        }
        const __nv_bfloat16* aH = Ah + (size_t)(tile0 * kMT + r) * 128 + ch;
        const __nv_bfloat16* aL = Al + (size_t)(tile0 * kMT + r) * 128 + ch;
        uint32_t adH = smem_u32(sAh + r * kLds + ch);
        uint32_t adL = smem_u32(sAl + r * kLds + ch);
#pragma unroll
        for (int q = 0; q < 4; q++) {
            cp_async16(adH + q * 16, aH + q * 8);
            cp_async16(adL + q * 16, aL + q * 8);
        }
    }
    cp_async_commit_wait();
    __syncthreads();

    const int wm = (wid & 1) * 32;
    const int wn = (wid >> 1) * 32;
    const uint32_t sAh_u = smem_u32(sAh);
    const uint32_t sBh_u = smem_u32(sBh);
    const uint32_t aLo = (uint32_t)(kMT * kLds * 2);
    const uint32_t bLo = (uint32_t)(128 * kLds * 2);

    const int aro = lane & 15;
    const int aco = (lane >> 4) * 8;
    const int bl  = lane & 15;
    const int bro = bl & 7;
    const int bco = ((bl >> 3) & 1) * 8;
    const int g = lane >> 2, tig = lane & 3;

    for (int it = 0; it < kTPB; it++) {
        const int m0 = (tile0 + it) * kMT;

        // prefetch next A tile into registers (in flight during MMAs)
        uint4 pf[8];
        if (it + 1 < kTPB) {
            const uint4* nH = reinterpret_cast<const uint4*>(
                Ah + (size_t)(m0 + kMT + r) * 128 + ch);
            const uint4* nL = reinterpret_cast<const uint4*>(
                Al + (size_t)(m0 + kMT + r) * 128 + ch);
#pragma unroll
            for (int q = 0; q < 4; q++) { pf[q] = nH[q]; pf[4 + q] = nL[q]; }
        }

        float acc[2][4][4];
#pragma unroll
        for (int mi = 0; mi < 2; mi++)
#pragma unroll
            for (int ni = 0; ni < 4; ni++)
#pragma unroll
                for (int j = 0; j < 4; j++) acc[mi][ni][j] = 0.f;

#pragma unroll
        for (int ks = 0; ks < 8; ks++) {
            uint32_t ah[2][4], al[2][4], bh[4][2], blo[4][2];
#pragma unroll
            for (int mi = 0; mi < 2; mi++) {
                uint32_t addr = sAh_u +
                    (uint32_t)(((wm + mi * 16 + aro) * kLds + ks * 16 + aco) * 2);
                ldsm_x4(ah[mi], addr);
                ldsm_x4(al[mi], addr + aLo);
            }
#pragma unroll
            for (int ni = 0; ni < 4; ni++) {
                uint32_t addr = sBh_u +
                    (uint32_t)(((wn + ni * 8 + bro) * kLds + ks * 16 + bco) * 2);
                ldsm_x2(bh[ni], addr);
                ldsm_x2(blo[ni], addr + bLo);
            }
#pragma unroll
            for (int mi = 0; mi < 2; mi++)
#pragma unroll
                for (int ni = 0; ni < 4; ni++) {
                    mma_bf16(acc[mi][ni], ah[mi], bh[ni]);
                    mma_bf16(acc[mi][ni], ah[mi], blo[ni]);
                    mma_bf16(acc[mi][ni], al[mi], bh[ni]);
                }
        }

        // epilogue
#pragma unroll
        for (int mi = 0; mi < 2; mi++) {
            int r0 = m0 + wm + mi * 16 + g;
            int r1 = r0 + 8;
            int or0 = rowmap ? rowmap[r0] : r0;
            int or1 = rowmap ? rowmap[r1] : r1;
#pragma unroll
            for (int ni = 0; ni < 4; ni++) {
                int col = wn + ni * 8 + 2 * tig;
                float b0 = bias[col];
                float b1 = bias[col + 1];
                float v00 = acc[mi][ni][0] + b0, v01 = acc[mi][ni][1] + b1;
                float v10 = acc[mi][ni][2] + b0, v11 = acc[mi][ni][3] + b1;
                if (OUTF32) {
                    *reinterpret_cast<float2*>(outF + (size_t)or0 * ldc + colbase + col) =
                        make_float2(v00, v01);
                    *reinterpret_cast<float2*>(outF + (size_t)or1 * ldc + colbase + col) =
                        make_float2(v10, v11);
                } else {
                    uint32_t h, l;
                    pack_split(v00, v01, h, l);
                    *reinterpret_cast<uint32_t*>(outH + (size_t)or0 * ldc + colbase + col) = h;
                    *reinterpret_cast<uint32_t*>(outL + (size_t)or0 * ldc + colbase + col) = l;
                    pack_split(v10, v11, h, l);
                    *reinterpret_cast<uint32_t*>(outH + (size_t)or1 * ldc + colbase + col) = h;
                    *reinterpret_cast<uint32_t*>(outL + (size_t)or1 * ldc + colbase + col) = l;
                }
            }
        }

        if (it + 1 < kTPB) {
            __syncthreads();   // everyone done reading sA
            uint4* dH = reinterpret_cast<uint4*>(sAh + r * kLds + ch);
            uint4* dL = reinterpret_cast<uint4*>(sAl + r * kLds + ch);
#pragma unroll
            for (int q = 0; q < 4; q++) { dH[q] = pf[q]; dL[q] = pf[4 + q]; }
            __syncthreads();
        }
    }
}

// fused Q/K/V projections: blockIdx.y = 0(Q),1(K),2(V); all slot-order inputs
__global__ __launch_bounds__(256)
void proj_fused() {
    int nt = blockIdx.y;
    const __nv_bfloat16* Ah = (nt == 2) ? g_Fh : g_QKih;
    const __nv_bfloat16* Al = (nt == 2) ? g_Fl : g_QKil;
    if (nt == 2)
        gemm_multi<false>(Ah, Al, 256, g_bias + 256, g_Vph, g_Vpl, nullptr,
                          128, 0, nullptr, blockIdx.x * kTPB);
    else
        gemm_multi<false>(Ah, Al, nt * 128, g_bias + nt * 128,
                          g_QKph, g_QKpl, nullptr, 256, nt * 128, nullptr,
                          blockIdx.x * kTPB);
}
// output projection (A = split O planes, fp32 out scattered to token order)
__global__ __launch_bounds__(256)
void proj_out(float* __restrict__ out) {
    gemm_multi<true>(g_Oh, g_Ol, 384, g_bias + 384, nullptr, nullptr, out,
                     128, 0, g_s2t, blockIdx.x * kTPB);
}

// ---------------- MMA attention: pure cp.async fill, one warp per head ----
template <int LV, int WPITCH>
__global__ __launch_bounds__(256)
void attn_mma(int slotbase, int slotoff) {
    constexpr int MT    = (LV + 15) / 16;
    constexpr int NT    = (LV + 7) / 8;
    constexpr int NTP   = (NT + 1) & ~1;
    constexpr int RowsP = ((LV + 15) / 16) * 16;
    constexpr int Lstr  = 136;
    constexpr int TSZ   = RowsP * Lstr;
    static_assert(NTP * 8 <= RowsP, "key pad fits");

    __nv_bfloat16* sQh = reinterpret_cast<__nv_bfloat16*>(smem_raw);
    __nv_bfloat16* sQl = sQh + TSZ;
    __nv_bfloat16* sKh = sQh + 2 * TSZ;
    __nv_bfloat16* sKl = sQh + 3 * TSZ;
    __nv_bfloat16* sVh = sQh + 4 * TSZ;
    __nv_bfloat16* sVl = sQh + 5 * TSZ;

    const int slot0 = slotbase + blockIdx.x * WPITCH + slotoff;
    const int tid = threadIdx.x;

    for (int t = tid; t < RowsP * 16; t += 256) {
        int j = t >> 4, c = t & 15;
        uint32_t off = (uint32_t)(j * Lstr * 2 + c * 16);
        if (j < LV) {
            size_t qk = (size_t)(slot0 + j) * 256 + c * 8;
            size_t vv = (size_t)(slot0 + j) * 128 + c * 8;
            cp_async16(smem_u32(sQh) + off, g_QKph + qk);
            cp_async16(smem_u32(sQl) + off, g_QKpl + qk);
            cp_async16(smem_u32(sKh) + off, g_QKph + qk + 128);
            cp_async16(smem_u32(sKl) + off, g_QKpl + qk + 128);
            cp_async16(smem_u32(sVh) + off, g_Vph + vv);
            cp_async16(smem_u32(sVl) + off, g_Vpl + vv);
        } else {
            uint4 z = make_uint4(0u, 0u, 0u, 0u);
            *reinterpret_cast<uint4*>(reinterpret_cast<char*>(sQh) + off) = z;
            *reinterpret_cast<uint4*>(reinterpret_cast<char*>(sQl) + off) = z;
            *reinterpret_cast<uint4*>(reinterpret_cast<char*>(sKh) + off) = z;
            *reinterpret_cast<uint4*>(reinterpret_cast<char*>(sKl) + off) = z;
            *reinterpret_cast<uint4*>(reinterpret_cast<char*>(sVh) + off) = z;
            *reinterpret_cast<uint4*>(reinterpret_cast<char*>(sVl) + off) = z;
        }
    }
    cp_async_commit_wait();
    __syncthreads();

    const int warp = tid >> 5, lane = tid & 31;
    const int hb = warp * 16;
    const int T = lane >> 2, i4 = lane & 3;
    const int bl = lane & 15;

    const uint32_t uQh = smem_u32(sQh);
    const uint32_t uKh = smem_u32(sKh);
    const uint32_t uVh = smem_u32(sVh);
    const uint32_t LO  = (uint32_t)(TSZ * 2);

#pragma unroll
    for (int mi = 0; mi < MT; mi++) {
        uint32_t qh[4], ql[4];
        {
            int row = mi * 16 + (lane & 15);
            uint32_t a = uQh + (uint32_t)((row * Lstr + hb + (lane >> 4) * 8) * 2);
            ldsm_x4(qh, a);
            ldsm_x4(ql, a + LO);
        }

        float s[NTP][4];
        float m0 = -1e30f, m1 = -1e30f;
#pragma unroll
        for (int nj = 0; nj < NT; nj++) {
            uint32_t kh[2], kl[2];
            int row = nj * 8 + (bl & 7);
            uint32_t a = uKh + (uint32_t)((row * Lstr + hb + ((bl >> 3) & 1) * 8) * 2);
            ldsm_x2(kh, a);
            ldsm_x2(kl, a + LO);
            s[nj][0] = s[nj][1] = s[nj][2] = s[nj][3] = 0.f;
            mma_bf16(s[nj], qh, kh);
            mma_bf16(s[nj], qh, kl);
            mma_bf16(s[nj], ql, kh);
            if (nj * 8 + 7 >= LV) {
                int j0 = nj * 8 + 2 * i4;
                if (j0 >= LV)     { s[nj][0] = -1e30f; s[nj][2] = -1e30f; }
                if (j0 + 1 >= LV) { s[nj][1] = -1e30f; s[nj][3] = -1e30f; }
            }
            m0 = fmaxf(m0, fmaxf(s[nj][0], s[nj][1]));
            m1 = fmaxf(m1, fmaxf(s[nj][2], s[nj][3]));
        }
        m0 = fmaxf(m0, __shfl_xor_sync(0xffffffffu, m0, 1));
        m0 = fmaxf(m0, __shfl_xor_sync(0xffffffffu, m0, 2));
        m1 = fmaxf(m1, __shfl_xor_sync(0xffffffffu, m1, 1));
        m1 = fmaxf(m1, __shfl_xor_sync(0xffffffffu, m1, 2));

        float sum0 = 0.f, sum1 = 0.f;
#pragma unroll
        for (int nj = 0; nj < NT; nj++) {
            s[nj][0] = __expf(s[nj][0] - m0);
            s[nj][1] = __expf(s[nj][1] - m0);
            s[nj][2] = __expf(s[nj][2] - m1);
            s[nj][3] = __expf(s[nj][3] - m1);
            sum0 += s[nj][0] + s[nj][1];
            sum1 += s[nj][2] + s[nj][3];
        }
#pragma unroll
        for (int nj = NT; nj < NTP; nj++)
            s[nj][0] = s[nj][1] = s[nj][2] = s[nj][3] = 0.f;
        sum0 += __shfl_xor_sync(0xffffffffu, sum0, 1);
        sum0 += __shfl_xor_sync(0xffffffffu, sum0, 2);
        sum1 += __shfl_xor_sync(0xffffffffu, sum1, 1);
        sum1 += __shfl_xor_sync(0xffffffffu, sum1, 2);

        float o0[4] = {0.f, 0.f, 0.f, 0.f};
        float o1[4] = {0.f, 0.f, 0.f, 0.f};
#pragma unroll
        for (int kj = 0; kj < NTP / 2; kj++) {
            uint32_t ah[4], al[4];
            pack_split(s[2 * kj][0],     s[2 * kj][1],     ah[0], al[0]);
            pack_split(s[2 * kj][2],     s[2 * kj][3],     ah[1], al[1]);
            pack_split(s[2 * kj + 1][0], s[2 * kj + 1][1], ah[2], al[2]);
            pack_split(s[2 * kj + 1][2], s[2 * kj + 1][3], ah[3], al[3]);
            int row = kj * 16 + bl;
            uint32_t a0 = uVh + (uint32_t)((row * Lstr + hb) * 2);
            uint32_t vh[2], vl[2];
            ldsm_x2_trans(vh, a0);
            ldsm_x2_trans(vl, a0 + LO);
            mma_bf16(o0, ah, vh);
            mma_bf16(o0, ah, vl);
            mma_bf16(o0, al, vh);
            ldsm_x2_trans(vh, a0 + 16);
            ldsm_x2_trans(vl, a0 + 16 + LO);
            mma_bf16(o1, ah, vh);
            mma_bf16(o1, ah, vl);
            mma_bf16(o1, al, vh);
        }

        float inv0 = 1.f / sum0, inv1 = 1.f / sum1;
        int r0 = mi * 16 + T, r1 = r0 + 8;
        int col = hb + 2 * i4;
        if (r0 < LV) {
            size_t base = (size_t)(slot0 + r0) * 128 + col;
            uint32_t h, l;
            pack_split(o0[0] * inv0, o0[1] * inv0, h, l);
            *reinterpret_cast<uint32_t*>(g_Oh + base) = h;
            *reinterpret_cast<uint32_t*>(g_Ol + base) = l;
            pack_split(o1[0] * inv0, o1[1] * inv0, h, l);
            *reinterpret_cast<uint32_t*>(g_Oh + base + 8) = h;
            *reinterpret_cast<uint32_t*>(g_Ol + base + 8) = l;
        }
        if (r1 < LV) {
            size_t base = (size_t)(slot0 + r1) * 128 + col;
            uint32_t h, l;
            pack_split(o0[2] * inv1, o0[3] * inv1, h, l);
            *reinterpret_cast<uint32_t*>(g_Oh + base) = h;
            *reinterpret_cast<uint32_t*>(g_Ol + base) = l;
            pack_split(o1[2] * inv1, o1[3] * inv1, h, l);
            *reinterpret_cast<uint32_t*>(g_Oh + base + 8) = h;
            *reinterpret_cast<uint32_t*>(g_Ol + base + 8) = l;
        }
    }
}

// ---------------- launch ----------------
template <int LV>
constexpr int attn_smem() { return 6 * (((LV + 15) / 16) * 16) * 136 * 2; }

extern "C" void kernel_launch(void* const* d_in, const int* in_sizes, int n_in,
                              void* d_out, int out_size) {
    const float* feat  = (const float*)d_in[0];
    const float* pos1  = (const float*)d_in[1];
    const float* pos2  = (const float*)d_in[2];
    const float* Wi    = (const float*)d_in[3];
    const float* bi    = (const float*)d_in[4];
    const float* Wo    = (const float*)d_in[5];
    const float* bo    = (const float*)d_in[6];
    const int*   inds1 = (const int*)d_in[7];
    const int*   inds2 = (const int*)d_in[8];
    float* out = (float*)d_out;

    cudaFuncSetAttribute(proj_fused, cudaFuncAttributeMaxDynamicSharedMemorySize, kTcSmem);
    cudaFuncSetAttribute(proj_out,   cudaFuncAttributeMaxDynamicSharedMemorySize, kTcSmem);
    cudaFuncSetAttribute((const void*)attn_mma<kL1, 54>,
                         cudaFuncAttributeMaxDynamicSharedMemorySize, attn_smem<kL1>());
    cudaFuncSetAttribute((const void*)attn_mma<kL1 / 2, 54>,
                         cudaFuncAttributeMaxDynamicSharedMemorySize, attn_smem<kL1 / 2>());
    cudaFuncSetAttribute((const void*)attn_mma<kL2, 150>,
                         cudaFuncAttributeMaxDynamicSharedMemorySize, attn_smem<kL2>());
    cudaFuncSetAttribute((const void*)attn_mma<kL2 / 2, 150>,
                         cudaFuncAttributeMaxDynamicSharedMemorySize, attn_smem<kL2 / 2>());

    // 1) weights + bias (Q pre-scaled) into bf16 hi/lo
    prep_w_kernel<<<256, 256>>>(Wi, Wo, bi, bo);
    // 2) gather: split(feat+pos) and split(feat) into slot space + s2t map
    gather_kernel<<<kNW1 + kNW2, 256>>>(feat, pos1, pos2, inds1, inds2);
    // 3) fused Q/K/V projections (B resident, 8 M-tiles/block, reg prefetch)
    proj_fused<<<dim3(kGrdX, 3), 256, kTcSmem>>>();
    // 4) windowed attention (even/odd split, compile-time Lv)
    attn_mma<kL1, 54><<<kNW1 / 2, 256, attn_smem<kL1>()>>>(0, 0);
    attn_mma<kL1 / 2, 54><<<kNW1 / 2, 256, attn_smem<kL1 / 2>()>>>(0, kL1);
    attn_mma<kL2, 150><<<kNW2 / 2, 256, attn_smem<kL2>()>>>(kN1, 0);
    attn_mma<kL2 / 2, 150><<<kNW2 / 2, 256, attn_smem<kL2 / 2>()>>>(kN1, kL2);
    // 5) output projection with row scatter (bijective -> no init/atomics)
    proj_out<<<kGrdX, 256, kTcSmem>>>(out);
}

// round 10
// speedup vs baseline: 4.3856x; 1.0529x over previous
#include <cuda_runtime.h>
#include <cuda_bf16.h>
#include <cstdint>

// ---------------- problem constants ----------------
constexpr int kD     = 128;
constexpr int kNH    = 8;
constexpr int kHD    = 16;
constexpr int kNW1   = 4096;
constexpr int kL1    = 36;
constexpr int kNW2   = 1024;
constexpr int kL2    = 100;
constexpr int kN1    = (kNW1 / 2) * (kL1 + kL1 / 2);   // 110592
constexpr int kN2    = (kNW2 / 2) * (kL2 + kL2 / 2);   // 76800
constexpr int kNTOK  = kN1 + kN2;                      // 187392 == 1464*128

static_assert(kNTOK % 128 == 0, "M tile");

extern __shared__ char smem_raw[];

// ---------------- device scratch (all inter-stage data pre-split bf16) -----
__device__ __nv_bfloat16 g_QKih[(size_t)kNTOK * 128];
__device__ __nv_bfloat16 g_QKil[(size_t)kNTOK * 128];
__device__ __nv_bfloat16 g_Fh  [(size_t)kNTOK * 128];   // feat, slot order
__device__ __nv_bfloat16 g_Fl  [(size_t)kNTOK * 128];
__device__ __nv_bfloat16 g_QKph[(size_t)kNTOK * 256];
__device__ __nv_bfloat16 g_QKpl[(size_t)kNTOK * 256];
__device__ __nv_bfloat16 g_Vph [(size_t)kNTOK * 128];
__device__ __nv_bfloat16 g_Vpl [(size_t)kNTOK * 128];
__device__ __nv_bfloat16 g_Oh  [(size_t)kNTOK * 128];
__device__ __nv_bfloat16 g_Ol  [(size_t)kNTOK * 128];
__device__ int   g_s2t [kNTOK];
__device__ float g_bias[512];
__device__ __nv_bfloat16 g_Wh[512 * 128];
__device__ __nv_bfloat16 g_Wl[512 * 128];

// ---------------- PTX helpers (sm_80+ generic) ----------------
__device__ __forceinline__ uint32_t smem_u32(const void* p) {
    uint32_t a;
    asm("{ .reg .u64 t; cvta.to.shared.u64 t, %1; cvt.u32.u64 %0, t; }"
        : "=r"(a) : "l"(p));
    return a;
}
__device__ __forceinline__ void cp_async16(uint32_t dst, const void* src) {
    asm volatile("cp.async.cg.shared.global [%0], [%1], 16;"
                 :: "r"(dst), "l"(src) : "memory");
}
__device__ __forceinline__ void cp_async_commit_wait() {
    asm volatile("cp.async.commit_group;" ::: "memory");
    asm volatile("cp.async.wait_group 0;" ::: "memory");
}
__device__ __forceinline__ void ldsm_x4(uint32_t* r, uint32_t a) {
    asm volatile("ldmatrix.sync.aligned.m8n8.x4.shared.b16 {%0,%1,%2,%3}, [%4];"
                 : "=r"(r[0]), "=r"(r[1]), "=r"(r[2]), "=r"(r[3]) : "r"(a));
}
__device__ __forceinline__ void ldsm_x2(uint32_t* r, uint32_t a) {
    asm volatile("ldmatrix.sync.aligned.m8n8.x2.shared.b16 {%0,%1}, [%2];"
                 : "=r"(r[0]), "=r"(r[1]) : "r"(a));
}
__device__ __forceinline__ void ldsm_x2_trans(uint32_t* r, uint32_t a) {
    asm volatile("ldmatrix.sync.aligned.m8n8.x2.trans.shared.b16 {%0,%1}, [%2];"
                 : "=r"(r[0]), "=r"(r[1]) : "r"(a));
}
__device__ __forceinline__ void mma_bf16(float* d, const uint32_t* a, const uint32_t* b) {
    asm volatile(
        "mma.sync.aligned.m16n8k16.row.col.f32.bf16.bf16.f32 "
        "{%0,%1,%2,%3}, {%4,%5,%6,%7}, {%8,%9}, {%0,%1,%2,%3};"
        : "+f"(d[0]), "+f"(d[1]), "+f"(d[2]), "+f"(d[3])
        : "r"(a[0]), "r"(a[1]), "r"(a[2]), "r"(a[3]), "r"(b[0]), "r"(b[1]));
}
__device__ __forceinline__ void pack_split(float x, float y, uint32_t& h, uint32_t& l) {
    __nv_bfloat162 hh = __floats2bfloat162_rn(x, y);
    __nv_bfloat162 ll = __floats2bfloat162_rn(x - __bfloat162float(hh.x),
                                              y - __bfloat162float(hh.y));
    h = *reinterpret_cast<uint32_t*>(&hh);
    l = *reinterpret_cast<uint32_t*>(&ll);
}
__device__ __forceinline__ void split_store(__nv_bfloat16* hi, __nv_bfloat16* lo,
                                            size_t idx, float4 v) {
    uint32_t h0, l0, h1, l1;
    pack_split(v.x, v.y, h0, l0);
    pack_split(v.z, v.w, h1, l1);
    *reinterpret_cast<uint2*>(hi + idx) = make_uint2(h0, h1);
    *reinterpret_cast<uint2*>(lo + idx) = make_uint2(l0, l1);
}

// ---------------- weight + bias prep (Q rows pre-scaled by 0.25) ----------
__global__ void prep_w_kernel(const float* __restrict__ Wi,
                              const float* __restrict__ Wo,
                              const float* __restrict__ bi,
                              const float* __restrict__ bo) {
    int t = blockIdx.x * 256 + threadIdx.x;
    if (t < 512) {
        float b = (t < 128) ? bi[t] * 0.25f : (t < 384 ? bi[t] : bo[t - 384]);
        g_bias[t] = b;
    }
    if (t >= 512 * 128) return;
    float w = (t < 384 * 128) ? Wi[t] : Wo[t - 384 * 128];
    if (t < 128 * 128) w *= 0.25f;   // fold score scale into Q
    __nv_bfloat16 h = __float2bfloat16(w);
    __nv_bfloat16 l = __float2bfloat16(w - __bfloat162float(h));
    g_Wh[t] = h;
    g_Wl[t] = l;
}

// ---------------- gather: split(feat+pos) and split(feat) -> slot planes --
__global__ __launch_bounds__(256)
void gather_kernel(const float* __restrict__ feat,
                   const float* __restrict__ pos1,
                   const float* __restrict__ pos2,
                   const int* __restrict__ inds1,
                   const int* __restrict__ inds2) {
    int w = blockIdx.x;
    int Lv, slot0;
    const int* inds;
    const float* pos;
    if (w < kNW1) {
        Lv    = (w & 1) ? (kL1 / 2) : kL1;
        slot0 = (w >> 1) * (kL1 + kL1 / 2) + (w & 1) * kL1;
        inds  = inds1 + w * kL1;
        pos   = pos1 + (size_t)w * kL1 * 128;
    } else {
        int w2 = w - kNW1;
        Lv    = (w2 & 1) ? (kL2 / 2) : kL2;
        slot0 = kN1 + (w2 >> 1) * (kL2 + kL2 / 2) + (w2 & 1) * kL2;
        inds  = inds2 + w2 * kL2;
        pos   = pos2 + (size_t)w2 * kL2 * 128;
    }
    for (int t = threadIdx.x; t < Lv * 32; t += 256) {
        int l = t >> 5, c = t & 31;
        int tok = inds[l];
        float4 f = reinterpret_cast<const float4*>(feat + (size_t)tok * 128)[c];
        float4 p = reinterpret_cast<const float4*>(pos + (size_t)l * 128)[c];
        float4 r;
        r.x = f.x + p.x; r.y = f.y + p.y; r.z = f.z + p.z; r.w = f.w + p.w;
        size_t idx = (size_t)(slot0 + l) * 128 + c * 4;
        split_store(g_QKih, g_QKil, idx, r);
        split_store(g_Fh, g_Fl, idx, f);
        if (c == 0) g_s2t[slot0 + l] = tok;
    }
}

// ---------------- multi-tile HMMA GEMM, B resident, A reg-prefetch --------
constexpr int kLds  = 136;
constexpr int kMT   = 64;
constexpr int kTcSmem = (2 * kMT + 2 * 128) * kLds * 2;   // 104448 B

template <bool OUTF32, int TPB>
__device__ __forceinline__ void gemm_multi(
    const __nv_bfloat16* __restrict__ Ah, const __nv_bfloat16* __restrict__ Al,
    int brow, const float* __restrict__ bias,
    __nv_bfloat16* __restrict__ outH, __nv_bfloat16* __restrict__ outL,
    float* __restrict__ outF,
    int ldc, int colbase, const int* __restrict__ rowmap, int tile0) {
    __nv_bfloat16* sAh = reinterpret_cast<__nv_bfloat16*>(smem_raw);
    __nv_bfloat16* sAl = sAh + kMT * kLds;
    __nv_bfloat16* sBh = sAh + 2 * kMT * kLds;
    __nv_bfloat16* sBl = sBh + 128 * kLds;

    const int tid = threadIdx.x;
    const int wid = tid >> 5, lane = tid & 31;
    const int r  = tid >> 2;
    const int ch = (tid & 3) * 32;

    {
        int n = tid >> 1, bch = (tid & 1) * 64;
        const __nv_bfloat16* srcH = g_Wh + (size_t)(brow + n) * 128 + bch;
        const __nv_bfloat16* srcL = g_Wl + (size_t)(brow + n) * 128 + bch;
        uint32_t dstH = smem_u32(sBh + n * kLds + bch);
        uint32_t dstL = smem_u32(sBl + n * kLds + bch);
#pragma unroll
        for (int q = 0; q < 8; q++) {
            cp_async16(dstH + q * 16, srcH + q * 8);
            cp_async16(dstL + q * 16, srcL + q * 8);
        }
        const __nv_bfloat16* aH = Ah + (size_t)(tile0 * kMT + r) * 128 + ch;
        const __nv_bfloat16* aL = Al + (size_t)(tile0 * kMT + r) * 128 + ch;
        uint32_t adH = smem_u32(sAh + r * kLds + ch);
        uint32_t adL = smem_u32(sAl + r * kLds + ch);
#pragma unroll
        for (int q = 0; q < 4; q++) {
            cp_async16(adH + q * 16, aH + q * 8);
            cp_async16(adL + q * 16, aL + q * 8);
        }
    }
    cp_async_commit_wait();
    __syncthreads();

    const int wm = (wid & 1) * 32;
    const int wn = (wid >> 1) * 32;
    const uint32_t sAh_u = smem_u32(sAh);
    const uint32_t sBh_u = smem_u32(sBh);
    const uint32_t aLo = (uint32_t)(kMT * kLds * 2);
    const uint32_t bLo = (uint32_t)(128 * kLds * 2);

    const int aro = lane & 15;
    const int aco = (lane >> 4) * 8;
    const int bl  = lane & 15;
    const int bro = bl & 7;
    const int bco = ((bl >> 3) & 1) * 8;
    const int g = lane >> 2, tig = lane & 3;

    for (int it = 0; it < TPB; it++) {
        const int m0 = (tile0 + it) * kMT;

        uint4 pf[8];
        if (it + 1 < TPB) {
            const uint4* nH = reinterpret_cast<const uint4*>(
                Ah + (size_t)(m0 + kMT + r) * 128 + ch);
            const uint4* nL = reinterpret_cast<const uint4*>(
                Al + (size_t)(m0 + kMT + r) * 128 + ch);
#pragma unroll
            for (int q = 0; q < 4; q++) { pf[q] = nH[q]; pf[4 + q] = nL[q]; }
        }

        float acc[2][4][4];
#pragma unroll
        for (int mi = 0; mi < 2; mi++)
#pragma unroll
            for (int ni = 0; ni < 4; ni++)
#pragma unroll
                for (int j = 0; j < 4; j++) acc[mi][ni][j] = 0.f;

#pragma unroll
        for (int ks = 0; ks < 8; ks++) {
            uint32_t ah[2][4], al[2][4], bh[4][2], blo[4][2];
#pragma unroll
            for (int mi = 0; mi < 2; mi++) {
                uint32_t addr = sAh_u +
                    (uint32_t)(((wm + mi * 16 + aro) * kLds + ks * 16 + aco) * 2);
                ldsm_x4(ah[mi], addr);
                ldsm_x4(al[mi], addr + aLo);
            }
#pragma unroll
            for (int ni = 0; ni < 4; ni++) {
                uint32_t addr = sBh_u +
                    (uint32_t)(((wn + ni * 8 + bro) * kLds + ks * 16 + bco) * 2);
                ldsm_x2(bh[ni], addr);
                ldsm_x2(blo[ni], addr + bLo);
            }
#pragma unroll
            for (int mi = 0; mi < 2; mi++)
#pragma unroll
                for (int ni = 0; ni < 4; ni++) {
                    mma_bf16(acc[mi][ni], ah[mi], bh[ni]);
                    mma_bf16(acc[mi][ni], ah[mi], blo[ni]);
                    mma_bf16(acc[mi][ni], al[mi], bh[ni]);
                }
        }

#pragma unroll
        for (int mi = 0; mi < 2; mi++) {
            int r0 = m0 + wm + mi * 16 + g;
            int r1 = r0 + 8;
            int or0 = rowmap ? rowmap[r0] : r0;
            int or1 = rowmap ? rowmap[r1] : r1;
#pragma unroll
            for (int ni = 0; ni < 4; ni++) {
                int col = wn + ni * 8 + 2 * tig;
                float b0 = bias[col];
                float b1 = bias[col + 1];
                float v00 = acc[mi][ni][0] + b0, v01 = acc[mi][ni][1] + b1;
                float v10 = acc[mi][ni][2] + b0, v11 = acc[mi][ni][3] + b1;
                if (OUTF32) {
                    *reinterpret_cast<float2*>(outF + (size_t)or0 * ldc + colbase + col) =
                        make_float2(v00, v01);
                    *reinterpret_cast<float2*>(outF + (size_t)or1 * ldc + colbase + col) =
                        make_float2(v10, v11);
                } else {
                    uint32_t h, l;
                    pack_split(v00, v01, h, l);
                    *reinterpret_cast<uint32_t*>(outH + (size_t)or0 * ldc + colbase + col) = h;
                    *reinterpret_cast<uint32_t*>(outL + (size_t)or0 * ldc + colbase + col) = l;
                    pack_split(v10, v11, h, l);
                    *reinterpret_cast<uint32_t*>(outH + (size_t)or1 * ldc + colbase + col) = h;
                    *reinterpret_cast<uint32_t*>(outL + (size_t)or1 * ldc + colbase + col) = l;
                }
            }
        }

        if (it + 1 < TPB) {
            __syncthreads();
            uint4* dH = reinterpret_cast<uint4*>(sAh + r * kLds + ch);
            uint4* dL = reinterpret_cast<uint4*>(sAl + r * kLds + ch);
#pragma unroll
            for (int q = 0; q < 4; q++) { dH[q] = pf[q]; dL[q] = pf[4 + q]; }
            __syncthreads();
        }
    }
}

constexpr int kTPBf = 8;
constexpr int kTPBo = 4;
constexpr int kGrdF = kNTOK / kMT / kTPBf;                // 366
constexpr int kGrdO = kNTOK / kMT / kTPBo;                // 732
static_assert(kNTOK % (kMT * kTPBf) == 0 && kNTOK % (kMT * kTPBo) == 0, "grid");

__global__ __launch_bounds__(256)
void proj_fused() {
    int nt = blockIdx.y;
    const __nv_bfloat16* Ah = (nt == 2) ? g_Fh : g_QKih;
    const __nv_bfloat16* Al = (nt == 2) ? g_Fl : g_QKil;
    if (nt == 2)
        gemm_multi<false, kTPBf>(Ah, Al, 256, g_bias + 256, g_Vph, g_Vpl, nullptr,
                                 128, 0, nullptr, blockIdx.x * kTPBf);
    else
        gemm_multi<false, kTPBf>(Ah, Al, nt * 128, g_bias + nt * 128,
                                 g_QKph, g_QKpl, nullptr, 256, nt * 128, nullptr,
                                 blockIdx.x * kTPBf);
}
__global__ __launch_bounds__(256)
void proj_out(float* __restrict__ out) {
    gemm_multi<true, kTPBo>(g_Oh, g_Ol, 384, g_bias + 384, nullptr, nullptr, out,
                            128, 0, g_s2t, blockIdx.x * kTPBo);
}

// ---------------- MMA attention ----------------
// NTHR=256: 1 warp/head. NTHR=512: 2 warps/head, Q-tiles split.
// KH: hoist K fragments across Q-tiles; VH: hoist V fragments too.
template <int LV, int WPITCH, int NTHR, bool KH, bool VH>
__global__ __launch_bounds__(NTHR)
void attn_mma(int slotbase, int slotoff) {
    constexpr int MT     = (LV + 15) / 16;
    constexpr int NT     = (LV + 7) / 8;
    constexpr int NTP    = (NT + 1) & ~1;
    constexpr int RowsP  = MT * 16;
    constexpr int Lstr   = 136;
    constexpr int TSZ    = RowsP * Lstr;
    constexpr int SLICES = NTHR / 256;
    constexpr int MT0    = (MT + SLICES - 1) / SLICES;
    static_assert(NTP * 8 <= RowsP, "key pad fits");

    __nv_bfloat16* sQh = reinterpret_cast<__nv_bfloat16*>(smem_raw);
    __nv_bfloat16* sQl = sQh + TSZ;
    __nv_bfloat16* sKh = sQh + 2 * TSZ;
    __nv_bfloat16* sKl = sQh + 3 * TSZ;
    __nv_bfloat16* sVh = sQh + 4 * TSZ;
    __nv_bfloat16* sVl = sQh + 5 * TSZ;

    const int slot0 = slotbase + blockIdx.x * WPITCH + slotoff;
    const int tid = threadIdx.x;

    // fill: valid rows via cp.async (6 planes); pad rows zero V only
    for (int t = tid; t < RowsP * 16; t += NTHR) {
        int j = t >> 4, c = t & 15;
        uint32_t off = (uint32_t)(j * Lstr * 2 + c * 16);
        if (j < LV) {
            size_t qk = (size_t)(slot0 + j) * 256 + c * 8;
            size_t vv = (size_t)(slot0 + j) * 128 + c * 8;
            cp_async16(smem_u32(sQh) + off, g_QKph + qk);
            cp_async16(smem_u32(sQl) + off, g_QKpl + qk);
            cp_async16(smem_u32(sKh) + off, g_QKph + qk + 128);
            cp_async16(smem_u32(sKl) + off, g_QKpl + qk + 128);
            cp_async16(smem_u32(sVh) + off, g_Vph + vv);
            cp_async16(smem_u32(sVl) + off, g_Vpl + vv);
        } else {
            uint4 z = make_uint4(0u, 0u, 0u, 0u);
            *reinterpret_cast<uint4*>(reinterpret_cast<char*>(sVh) + off) = z;
            *reinterpret_cast<uint4*>(reinterpret_cast<char*>(sVl) + off) = z;
        }
    }
    cp_async_commit_wait();
    __syncthreads();

    const int warp = tid >> 5, lane = tid & 31;
    const int head = warp & 7, slice = warp >> 3;
    const int hb = head * 16;
    const int T = lane >> 2, i4 = lane & 3;
    const int bl = lane & 15;

    const uint32_t uQh = smem_u32(sQh);
    const uint32_t uKh = smem_u32(sKh);
    const uint32_t uVh = smem_u32(sVh);
    const uint32_t LO  = (uint32_t)(TSZ * 2);

    // hoisted K fragments
    constexpr int KNT = KH ? NT : 1;
    uint32_t khA[KNT][2], klA[KNT][2];
    if (KH) {
#pragma unroll
        for (int nj = 0; nj < NT; nj++) {
            int row = nj * 8 + (bl & 7);
            uint32_t a = uKh + (uint32_t)((row * Lstr + hb + ((bl >> 3) & 1) * 8) * 2);
            ldsm_x2(khA[nj], a);
            ldsm_x2(klA[nj], a + LO);
        }
    }
    // hoisted V fragments (two 8-col halves per kj)
    constexpr int KJ = NTP / 2;
    constexpr int VKJ = VH ? KJ : 1;
    uint32_t vhA[VKJ][2], vlA[VKJ][2], vhB[VKJ][2], vlB[VKJ][2];
    if (VH) {
#pragma unroll
        for (int kj = 0; kj < KJ; kj++) {
            uint32_t a0 = uVh + (uint32_t)(((kj * 16 + bl) * Lstr + hb) * 2);
            ldsm_x2_trans(vhA[kj], a0);
            ldsm_x2_trans(vlA[kj], a0 + LO);
            ldsm_x2_trans(vhB[kj], a0 + 16);
            ldsm_x2_trans(vlB[kj], a0 + 16 + LO);
        }
    }

    const int miEnd = (slice + 1) * MT0 < MT ? (slice + 1) * MT0 : MT;
#pragma unroll
    for (int mi = slice * MT0; mi < miEnd; mi++) {
        uint32_t qh[4], ql[4];
        {
            int row = mi * 16 + (lane & 15);
            uint32_t a = uQh + (uint32_t)((row * Lstr + hb + (lane >> 4) * 8) * 2);
            ldsm_x4(qh, a);
            ldsm_x4(ql, a + LO);
        }

        float s[NTP][4];
        float m0 = -1e30f, m1 = -1e30f;
#pragma unroll
        for (int nj = 0; nj < NT; nj++) {
            uint32_t kh[2], kl[2];
            if (KH) {
                kh[0] = khA[nj][0]; kh[1] = khA[nj][1];
                kl[0] = klA[nj][0]; kl[1] = klA[nj][1];
            } else {
                int row = nj * 8 + (bl & 7);
                uint32_t a = uKh + (uint32_t)((row * Lstr + hb + ((bl >> 3) & 1) * 8) * 2);
                ldsm_x2(kh, a);
                ldsm_x2(kl, a + LO);
            }
            s[nj][0] = s[nj][1] = s[nj][2] = s[nj][3] = 0.f;
            mma_bf16(s[nj], qh, kh);
            mma_bf16(s[nj], qh, kl);
            mma_bf16(s[nj], ql, kh);
            if (nj * 8 + 7 >= LV) {
                int j0 = nj * 8 + 2 * i4;
                if (j0 >= LV)     { s[nj][0] = -1e30f; s[nj][2] = -1e30f; }
                if (j0 + 1 >= LV) { s[nj][1] = -1e30f; s[nj][3] = -1e30f; }
            }
            m0 = fmaxf(m0, fmaxf(s[nj][0], s[nj][1]));
            m1 = fmaxf(m1, fmaxf(s[nj][2], s[nj][3]));
        }
        m0 = fmaxf(m0, __shfl_xor_sync(0xffffffffu, m0, 1));
        m0 = fmaxf(m0, __shfl_xor_sync(0xffffffffu, m0, 2));
        m1 = fmaxf(m1, __shfl_xor_sync(0xffffffffu, m1, 1));
        m1 = fmaxf(m1, __shfl_xor_sync(0xffffffffu, m1, 2));

        float sum0 = 0.f, sum1 = 0.f;
#pragma unroll
        for (int nj = 0; nj < NT; nj++) {
            s[nj][0] = __expf(s[nj][0] - m0);
            s[nj][1] = __expf(s[nj][1] - m0);
            s[nj][2] = __expf(s[nj][2] - m1);
            s[nj][3] = __expf(s[nj][3] - m1);
            sum0 += s[nj][0] + s[nj][1];
            sum1 += s[nj][2] + s[nj][3];
        }
#pragma unroll
        for (int nj = NT; nj < NTP; nj++)
            s[nj][0] = s[nj][1] = s[nj][2] = s[nj][3] = 0.f;
        sum0 += __shfl_xor_sync(0xffffffffu, sum0, 1);
        sum0 += __shfl_xor_sync(0xffffffffu, sum0, 2);
        sum1 += __shfl_xor_sync(0xffffffffu, sum1, 1);
        sum1 += __shfl_xor_sync(0xffffffffu, sum1, 2);

        float o0[4] = {0.f, 0.f, 0.f, 0.f};
        float o1[4] = {0.f, 0.f, 0.f, 0.f};
#pragma unroll
        for (int kj = 0; kj < KJ; kj++) {
            uint32_t ah[4], al[4];
            pack_split(s[2 * kj][0],     s[2 * kj][1],     ah[0], al[0]);
            pack_split(s[2 * kj][2],     s[2 * kj][3],     ah[1], al[1]);
            pack_split(s[2 * kj + 1][0], s[2 * kj + 1][1], ah[2], al[2]);
            pack_split(s[2 * kj + 1][2], s[2 * kj + 1][3], ah[3], al[3]);
            uint32_t vh0[2], vl0[2], vh1[2], vl1[2];
            if (VH) {
                vh0[0] = vhA[kj][0]; vh0[1] = vhA[kj][1];
                vl0[0] = vlA[kj][0]; vl0[1] = vlA[kj][1];
                vh1[0] = vhB[kj][0]; vh1[1] = vhB[kj][1];
                vl1[0] = vlB[kj][0]; vl1[1] = vlB[kj][1];
            } else {
                uint32_t a0 = uVh + (uint32_t)(((kj * 16 + bl) * Lstr + hb) * 2);
                ldsm_x2_trans(vh0, a0);
                ldsm_x2_trans(vl0, a0 + LO);
                ldsm_x2_trans(vh1, a0 + 16);
                ldsm_x2_trans(vl1, a0 + 16 + LO);
            }
            mma_bf16(o0, ah, vh0);
            mma_bf16(o0, ah, vl0);
            mma_bf16(o0, al, vh0);
            mma_bf16(o1, ah, vh1);
            mma_bf16(o1, ah, vl1);
            mma_bf16(o1, al, vh1);
        }

        float inv0 = 1.f / sum0, inv1 = 1.f / sum1;
        int r0 = mi * 16 + T, r1 = r0 + 8;
        int col = hb + 2 * i4;
        if (r0 < LV) {
            size_t base = (size_t)(slot0 + r0) * 128 + col;
            uint32_t h, l;
            pack_split(o0[0] * inv0, o0[1] * inv0, h, l);
            *reinterpret_cast<uint32_t*>(g_Oh + base) = h;
            *reinterpret_cast<uint32_t*>(g_Ol + base) = l;
            pack_split(o1[0] * inv0, o1[1] * inv0, h, l);
            *reinterpret_cast<uint32_t*>(g_Oh + base + 8) = h;
            *reinterpret_cast<uint32_t*>(g_Ol + base + 8) = l;
        }
        if (r1 < LV) {
            size_t base = (size_t)(slot0 + r1) * 128 + col;
            uint32_t h, l;
            pack_split(o0[2] * inv1, o0[3] * inv1, h, l);
            *reinterpret_cast<uint32_t*>(g_Oh + base) = h;
            *reinterpret_cast<uint32_t*>(g_Ol + base) = l;
            pack_split(o1[2] * inv1, o1[3] * inv1, h, l);
            *reinterpret_cast<uint32_t*>(g_Oh + base + 8) = h;
            *reinterpret_cast<uint32_t*>(g_Ol + base + 8) = l;
        }
    }
}

// ---------------- launch ----------------
template <int LV>
constexpr int attn_smem() { return 6 * (((LV + 15) / 16) * 16) * 136 * 2; }

extern "C" void kernel_launch(void* const* d_in, const int* in_sizes, int n_in,
                              void* d_out, int out_size) {
    const float* feat  = (const float*)d_in[0];
    const float* pos1  = (const float*)d_in[1];
    const float* pos2  = (const float*)d_in[2];
    const float* Wi    = (const float*)d_in[3];
    const float* bi    = (const float*)d_in[4];
    const float* Wo    = (const float*)d_in[5];
    const float* bo    = (const float*)d_in[6];
    const int*   inds1 = (const int*)d_in[7];
    const int*   inds2 = (const int*)d_in[8];
    float* out = (float*)d_out;

    cudaFuncSetAttribute(proj_fused, cudaFuncAttributeMaxDynamicSharedMemorySize, kTcSmem);
    cudaFuncSetAttribute(proj_out,   cudaFuncAttributeMaxDynamicSharedMemorySize, kTcSmem);
    cudaFuncSetAttribute((const void*)attn_mma<kL1, 54, 256, true, true>,
                         cudaFuncAttributeMaxDynamicSharedMemorySize, attn_smem<kL1>());
    cudaFuncSetAttribute((const void*)attn_mma<kL1 / 2, 54, 256, true, true>,
                         cudaFuncAttributeMaxDynamicSharedMemorySize, attn_smem<kL1 / 2>());
    cudaFuncSetAttribute((const void*)attn_mma<kL2, 150, 512, false, false>,
                         cudaFuncAttributeMaxDynamicSharedMemorySize, attn_smem<kL2>());
    cudaFuncSetAttribute((const void*)attn_mma<kL2 / 2, 150, 256, true, false>,
                         cudaFuncAttributeMaxDynamicSharedMemorySize, attn_smem<kL2 / 2>());

    // 1) weights + bias (Q pre-scaled) into bf16 hi/lo
    prep_w_kernel<<<256, 256>>>(Wi, Wo, bi, bo);
    // 2) gather: split(feat+pos) and split(feat) into slot space + s2t map
    gather_kernel<<<kNW1 + kNW2, 256>>>(feat, pos1, pos2, inds1, inds2);
    // 3) fused Q/K/V projections (B resident, 8 M-tiles/block, reg prefetch)
    proj_fused<<<dim3(kGrdF, 3), 256, kTcSmem>>>();
    // 4) windowed attention
    attn_mma<kL1, 54, 256, true, true><<<kNW1 / 2, 256, attn_smem<kL1>()>>>(0, 0);
    attn_mma<kL1 / 2, 54, 256, true, true><<<kNW1 / 2, 256, attn_smem<kL1 / 2>()>>>(0, kL1);
    attn_mma<kL2, 150, 512, false, false><<<kNW2 / 2, 512, attn_smem<kL2>()>>>(kN1, 0);
    attn_mma<kL2 / 2, 150, 256, true, false><<<kNW2 / 2, 256, attn_smem<kL2 / 2>()>>>(kN1, kL2);
    // 5) output projection with row scatter (bijective -> no init/atomics)
    proj_out<<<kGrdO, 256, kTcSmem>>>(out);
}